// round 7
// baseline (speedup 1.0000x reference)
#include <cuda_runtime.h>
#include <cuda_bf16.h>
#include <cstdint>
#include <math.h>

#define SEQ   8
#define FEAT  2048
#define DOUT  1152
#define TLEN  28
#define WAY   5
#define SHOT  5
#define NQv   500
#define NSv   25
#define RQ    (NQv*SEQ)     /* 4000 query frame rows   */
#define RS    (NSv*SEQ)     /* 200 support frame rows  */
#define RALL  (RQ+RS)       /* 4200                    */
#define MQ    (NQv*TLEN)    /* 14000 query tuples      */
#define MS    (NSv*TLEN)    /* 700 support tuples      */

// padded dims (multiples of 128 for the tensor GEMM; no bounds checks needed)
#define MTP   4224          /* padded frame rows                  */
#define NTP   4608          /* 4 planes x 1152 output cols        */
#define MQP   14080         /* padded query tuples                */
#define MSP   768           /* padded support tuples              */

// ---------------- scratch (static device memory; no allocations) -------------
__device__ __nv_bfloat16 d_Xh [MTP*FEAT];
__device__ __nv_bfloat16 d_Xl [MTP*FEAT];
__device__ __nv_bfloat16 d_Wth[NTP*FEAT];
__device__ __nv_bfloat16 d_Wtl[NTP*FEAT];
__device__ float         d_P  [(size_t)MTP*NTP];   // 4-plane frame projections
__device__ __nv_bfloat16 d_QKh[(size_t)MQP*DOUT];
__device__ __nv_bfloat16 d_QKl[(size_t)MQP*DOUT];
__device__ __nv_bfloat16 d_QVh[(size_t)MQP*DOUT];
__device__ __nv_bfloat16 d_QVl[(size_t)MQP*DOUT];
__device__ __nv_bfloat16 d_SKh[(size_t)MSP*DOUT];
__device__ __nv_bfloat16 d_SKl[(size_t)MSP*DOUT];
__device__ __nv_bfloat16 d_SVh[(size_t)MSP*DOUT];
__device__ __nv_bfloat16 d_SVl[(size_t)MSP*DOUT];
__device__ float         d_SVf[(size_t)MSP*DOUT];
__device__ float         d_S  [(size_t)MQP*MSP];
__device__ float         d_Wm [(size_t)MQP*MSP];
__device__ float         d_qn [MQ];
__device__ float         d_G  [WAY*140*140];

__constant__ int c_tup[TLEN*2] = {
  0,1, 0,2, 0,3, 0,4, 0,5, 0,6, 0,7,
  1,2, 1,3, 1,4, 1,5, 1,6, 1,7,
  2,3, 2,4, 2,5, 2,6, 2,7,
  3,4, 3,5, 3,6, 3,7,
  4,5, 4,6, 4,7,
  5,6, 5,7,
  6,7
};

// ======================= generic-target helpers ==============================
__device__ __forceinline__ uint32_t smem_u32(const void* p) {
  uint32_t a;
  asm("{ .reg .u64 t; cvta.to.shared.u64 t, %1; cvt.u32.u64 %0, t; }" : "=r"(a) : "l"(p));
  return a;
}
__device__ __forceinline__ void ldsm4(uint32_t& r0, uint32_t& r1, uint32_t& r2,
                                      uint32_t& r3, uint32_t a) {
  asm volatile("ldmatrix.sync.aligned.m8n8.x4.shared.b16 {%0,%1,%2,%3}, [%4];"
               : "=r"(r0), "=r"(r1), "=r"(r2), "=r"(r3) : "r"(a));
}
__device__ __forceinline__ void mma_bf16(float* c, const uint32_t* a, const uint32_t* b) {
  asm volatile("mma.sync.aligned.m16n8k16.row.col.f32.bf16.bf16.f32 "
               "{%0,%1,%2,%3}, {%4,%5,%6,%7}, {%8,%9}, {%0,%1,%2,%3};"
               : "+f"(c[0]), "+f"(c[1]), "+f"(c[2]), "+f"(c[3])
               : "r"(a[0]), "r"(a[1]), "r"(a[2]), "r"(a[3]), "r"(b[0]), "r"(b[1]));
}

// ======================= bf16x3 HMMA GEMM ====================================
// C[M,N] = Ah*Bh^T + Ah*Bl^T + Al*Bh^T   (A:[M,K], B:[N,K], K-contiguous,
// all dims multiples of 128 / K multiple of 64; fp32 C)
#define STAGES  3
#define TILE_B  16384                 /* 128 rows x 64 bf16 (128B rows) */
#define STAGE_B (4*TILE_B)
#define GSMEM   (STAGES*STAGE_B)      /* 192 KB */

__device__ __forceinline__ void load_stage(
    const __nv_bfloat16* __restrict__ Ah, const __nv_bfloat16* __restrict__ Al,
    const __nv_bfloat16* __restrict__ Bh, const __nv_bfloat16* __restrict__ Bl,
    uint32_t stage, int m0, int n0, int k0, int K, int tid)
{
  #pragma unroll
  for (int i = 0; i < 16; i++) {
    int id   = tid + i * 256;
    int tile = id >> 10;                      // 0:Ah 1:Al 2:Bh 3:Bl
    int row  = (id >> 3) & 127;
    int c16  = id & 7;                        // 16B chunk within 128B row
    const __nv_bfloat16* base = (tile == 0) ? Ah : (tile == 1) ? Al
                              : (tile == 2) ? Bh : Bl;
    int r = ((tile < 2) ? m0 : n0) + row;
    const __nv_bfloat16* src = base + (size_t)r * K + k0 + c16 * 8;
    uint32_t dst = stage + tile * TILE_B + (row << 7) + ((c16 ^ (row & 7)) << 4);
    asm volatile("cp.async.cg.shared.global [%0], [%1], 16;" :: "r"(dst), "l"(src) : "memory");
  }
  asm volatile("cp.async.commit_group;" ::: "memory");
}

__global__ void __launch_bounds__(256)
gemm3_mma(const __nv_bfloat16* __restrict__ Ah, const __nv_bfloat16* __restrict__ Al,
          const __nv_bfloat16* __restrict__ Bh, const __nv_bfloat16* __restrict__ Bl,
          float* __restrict__ C, int K, int ldc)
{
  extern __shared__ char smem[];
  const uint32_t sb = smem_u32(smem);
  const int tid  = threadIdx.x;
  const int lane = tid & 31;
  const int wid  = tid >> 5;
  const int wm   = wid & 1;           // 2 m-blocks of 64
  const int wn   = wid >> 1;          // 4 n-blocks of 32
  const int m0 = blockIdx.x * 128, n0 = blockIdx.y * 128;
  const int NC = K >> 6;

  // ldmatrix per-lane addressing components
  const int q     = lane >> 3;
  const int lrow  = (q & 1) * 8 + (lane & 7);
  const int khalf = q >> 1;

  float acc[4][4][4];
  #pragma unroll
  for (int a = 0; a < 4; a++)
    #pragma unroll
    for (int b = 0; b < 4; b++)
      #pragma unroll
      for (int d = 0; d < 4; d++) acc[a][b][d] = 0.f;

  load_stage(Ah, Al, Bh, Bl, sb + 0 * STAGE_B, m0, n0, 0,  K, tid);
  load_stage(Ah, Al, Bh, Bl, sb + 1 * STAGE_B, m0, n0, 64, K, tid);

  for (int c = 0; c < NC; c++) {
    asm volatile("cp.async.wait_group 1;" ::: "memory");
    __syncthreads();
    if (c + 2 < NC)
      load_stage(Ah, Al, Bh, Bl, sb + ((c + 2) % STAGES) * STAGE_B,
                 m0, n0, (c + 2) * 64, K, tid);
    else
      asm volatile("cp.async.commit_group;" ::: "memory");   // keep group count uniform

    const uint32_t st = sb + (c % STAGES) * STAGE_B;
    #pragma unroll
    for (int ks = 0; ks < 4; ks++) {
      const int cc = 2 * ks + khalf;
      uint32_t aH[4][4], aL[4][4];
      #pragma unroll
      for (int mi = 0; mi < 4; mi++) {
        int r = wm * 64 + mi * 16 + lrow;
        uint32_t ad = st + (r << 7) + ((cc ^ (r & 7)) << 4);
        ldsm4(aH[mi][0], aH[mi][1], aH[mi][2], aH[mi][3], ad);
        ldsm4(aL[mi][0], aL[mi][1], aL[mi][2], aL[mi][3], ad + TILE_B);
      }
      uint32_t bH[4][2], bL[4][2];
      #pragma unroll
      for (int g = 0; g < 2; g++) {
        int r = wn * 32 + g * 16 + lrow;
        uint32_t bd = st + 2 * TILE_B + (r << 7) + ((cc ^ (r & 7)) << 4);
        uint32_t t0, t1, t2, t3;
        ldsm4(t0, t1, t2, t3, bd);
        bH[2*g][0] = t0; bH[2*g][1] = t2; bH[2*g+1][0] = t1; bH[2*g+1][1] = t3;
        ldsm4(t0, t1, t2, t3, bd + TILE_B);
        bL[2*g][0] = t0; bL[2*g][1] = t2; bL[2*g+1][0] = t1; bL[2*g+1][1] = t3;
      }
      // RAW-hazard-free ordering: each product sweeps all 16 independent
      // accumulators before any acc tile is revisited (16 indep HMMAs between
      // reuses instead of 3 chained on the same accumulator).
      #pragma unroll
      for (int mi = 0; mi < 4; mi++)
        #pragma unroll
        for (int nj = 0; nj < 4; nj++)
          mma_bf16(acc[mi][nj], aH[mi], bH[nj]);
      #pragma unroll
      for (int mi = 0; mi < 4; mi++)
        #pragma unroll
        for (int nj = 0; nj < 4; nj++)
          mma_bf16(acc[mi][nj], aH[mi], bL[nj]);
      #pragma unroll
      for (int mi = 0; mi < 4; mi++)
        #pragma unroll
        for (int nj = 0; nj < 4; nj++)
          mma_bf16(acc[mi][nj], aL[mi], bH[nj]);
    }
  }

  // epilogue: fragment -> C
  #pragma unroll
  for (int mi = 0; mi < 4; mi++) {
    int r = m0 + wm * 64 + mi * 16 + (lane >> 2);
    #pragma unroll
    for (int nj = 0; nj < 4; nj++) {
      int col = n0 + wn * 32 + nj * 8 + ((lane & 3) << 1);
      *(float2*)&C[(size_t)r * ldc + col]       = make_float2(acc[mi][nj][0], acc[mi][nj][1]);
      *(float2*)&C[(size_t)(r + 8) * ldc + col] = make_float2(acc[mi][nj][2], acc[mi][nj][3]);
    }
  }
}

// ---------------- reductions -------------------------------------------------
__device__ __forceinline__ float warpReduceSum(float v) {
  #pragma unroll
  for (int o = 16; o; o >>= 1) v += __shfl_xor_sync(0xffffffffu, v, o);
  return v;
}
__device__ __forceinline__ float warpReduceMax(float v) {
  #pragma unroll
  for (int o = 16; o; o >>= 1) v = fmaxf(v, __shfl_xor_sync(0xffffffffu, v, o));
  return v;
}
__device__ float blockReduceSum(float v, float* red) {
  int lane = threadIdx.x & 31, w = threadIdx.x >> 5;
  int nw = (blockDim.x + 31) >> 5;
  v = warpReduceSum(v);
  __syncthreads();
  if (lane == 0) red[w] = v;
  __syncthreads();
  if (w == 0) {
    float r = (lane < nw) ? red[lane] : 0.f;
    r = warpReduceSum(r);
    if (lane == 0) red[0] = r;
  }
  __syncthreads();
  return red[0];
}
__device__ float blockReduceMax(float v, float* red) {
  int lane = threadIdx.x & 31, w = threadIdx.x >> 5;
  int nw = (blockDim.x + 31) >> 5;
  v = warpReduceMax(v);
  __syncthreads();
  if (lane == 0) red[w] = v;
  __syncthreads();
  if (w == 0) {
    float r = (lane < nw) ? red[lane] : -INFINITY;
    r = warpReduceMax(r);
    if (lane == 0) red[0] = r;
  }
  __syncthreads();
  return red[0];
}

// ---------------- kernels 1a/1b: frames + PE, split to bf16 hi/lo ------------
__device__ __forceinline__ void prep_one(int idx, float v) {
  int d  = idx & (FEAT - 1);
  int r  = idx >> 11;
  int fr = r & 7;
  float freq = __expf((float)(d & ~1) * (-9.210340371976184f / 2048.0f));
  float ang  = (float)fr * freq;
  float pe   = (d & 1) ? __cosf(ang) : __sinf(ang);
  float x = v + pe;
  __nv_bfloat16 h = __float2bfloat16(x);
  d_Xh[idx] = h;
  d_Xl[idx] = __float2bfloat16(x - __bfloat162float(h));
}
__global__ void prep_q(const float* __restrict__ q) {
  int idx = blockIdx.x * blockDim.x + threadIdx.x;
  if (idx >= RQ * FEAT) return;
  prep_one(idx, q[idx]);
}
__global__ void prep_s(const float* __restrict__ s) {
  int idx = blockIdx.x * blockDim.x + threadIdx.x;
  if (idx >= (MTP - RQ) * FEAT) return;
  int gidx = idx + RQ * FEAT;
  if (idx >= RS * FEAT) {                    // pad rows -> zeros
    d_Xh[gidx] = __float2bfloat16(0.f);
    d_Xl[gidx] = __float2bfloat16(0.f);
    return;
  }
  prep_one(gidx, s[idx]);
}

// ---------------- kernel 2: transpose+split weights into [NTP, FEAT] ---------
// z = plane: 0,1 from kw ; 2,3 from vw
__global__ void split_w(const float* __restrict__ kw, const float* __restrict__ vw) {
  __shared__ float tile[32][33];
  int p = blockIdx.z;
  const float* w = (p < 2) ? kw : vw;
  int k0 = blockIdx.x * 32, c0 = blockIdx.y * 32;
  int rbase = (p & 1) * FEAT;
  int tx = threadIdx.x, ty = threadIdx.y;  // 32 x 8
  #pragma unroll
  for (int i = 0; i < 32; i += 8)
    tile[ty + i][tx] = w[(size_t)(rbase + k0 + ty + i) * DOUT + c0 + tx];
  __syncthreads();
  #pragma unroll
  for (int i = 0; i < 32; i += 8) {
    float v = tile[tx][ty + i];
    __nv_bfloat16 h = __float2bfloat16(v);
    size_t o = (size_t)(p * DOUT + c0 + ty + i) * FEAT + k0 + tx;
    d_Wth[o] = h;
    d_Wtl[o] = __float2bfloat16(v - __bfloat162float(h));
  }
}

// ---------------- kernel 3: fp32 sgemm, batched over z (Gram only) -----------
#define BM 64
#define BN 64
#define BK 16
__global__ void __launch_bounds__(256)
sgemm_nt_gram(const float* __restrict__ Abase, float* __restrict__ Cbase,
              int M, int N, int K, size_t strideA, size_t strideC) {
  const float* A = Abase + blockIdx.z * strideA;
  const float* B = A;
  float* C = Cbase + blockIdx.z * strideC;
  __shared__ __align__(16) float As[BK][BM + 4];
  __shared__ __align__(16) float Bs[BK][BN + 4];
  int tid = threadIdx.x;
  int tx = tid & 15, ty = tid >> 4;
  int m0 = blockIdx.x * BM, n0 = blockIdx.y * BN;
  int lr = tid >> 2;
  int lc = (tid & 3) << 2;
  float acc[4][4] = {};
  const float* Aptr = A + (size_t)(m0 + lr) * K + lc;
  const float* Bptr = B + (size_t)(n0 + lr) * K + lc;
  bool am = (m0 + lr) < M;
  bool bn = (n0 + lr) < N;
  for (int k0 = 0; k0 < K; k0 += BK) {
    float4 av = am ? *(const float4*)(Aptr + k0) : make_float4(0, 0, 0, 0);
    float4 bv = bn ? *(const float4*)(Bptr + k0) : make_float4(0, 0, 0, 0);
    As[lc + 0][lr] = av.x; As[lc + 1][lr] = av.y;
    As[lc + 2][lr] = av.z; As[lc + 3][lr] = av.w;
    Bs[lc + 0][lr] = bv.x; Bs[lc + 1][lr] = bv.y;
    Bs[lc + 2][lr] = bv.z; Bs[lc + 3][lr] = bv.w;
    __syncthreads();
    #pragma unroll
    for (int k = 0; k < BK; k++) {
      float4 a4 = *(const float4*)&As[k][ty << 2];
      float4 b4 = *(const float4*)&Bs[k][tx << 2];
      float ar[4] = {a4.x, a4.y, a4.z, a4.w};
      float br[4] = {b4.x, b4.y, b4.z, b4.w};
      #pragma unroll
      for (int i = 0; i < 4; i++)
        #pragma unroll
        for (int j = 0; j < 4; j++)
          acc[i][j] += ar[i] * br[j];
    }
    __syncthreads();
  }
  #pragma unroll
  for (int i = 0; i < 4; i++) {
    int m = m0 + (ty << 2) + i;
    if (m >= M) continue;
    #pragma unroll
    for (int j = 0; j < 4; j++) {
      int n = n0 + (tx << 2) + j;
      if (n < N) C[(size_t)m * N + n] = acc[i][j];
    }
  }
}

// ---------------- kernel 4: per-item tuple combine + LN(K) + splits ----------
// One block per clip (525 total). Loads the clip's 8 frame-rows of d_P (all 4
// planes, 147 KB) into smem ONCE, then emits all 28 tuples from smem.
#define CSMEM ((8*NTP + DOUT + 32) * 4)
__global__ void __launch_bounds__(256)
combine2(const float* __restrict__ kb, const float* __restrict__ vb,
         const float* __restrict__ gamma, const float* __restrict__ beta) {
  extern __shared__ float cs[];
  float* sP  = cs;                 // 8 * 4608
  float* kv  = cs + 8 * NTP;       // 1152
  float* red = kv + DOUT;          // 32
  const int item = blockIdx.x;
  const bool isQ = item < NQv;
  const int tid = threadIdx.x;
  const float* src = d_P + (size_t)item * SEQ * NTP;
  for (int i = tid * 4; i < SEQ * NTP; i += 256 * 4)
    *(float4*)&sP[i] = *(const float4*)&src[i];
  __syncthreads();
  const int mBase = isQ ? item * TLEN : (item - NQv) * TLEN;
  for (int t = 0; t < TLEN; t++) {
    int fi = c_tup[2 * t], fj = c_tup[2 * t + 1];
    const float* pA = sP + fi * NTP;
    const float* pB = sP + fj * NTP;
    size_t mOff = (size_t)(mBase + t) * DOUT;
    float s1 = 0.f, s2 = 0.f, qacc = 0.f;
    for (int d = tid; d < DOUT; d += 256) {
      float x = pA[d] + pB[DOUT + d] + kb[d];
      kv[d] = x; s1 += x; s2 += x * x;
      float y = pA[2 * DOUT + d] + pB[3 * DOUT + d] + vb[d];
      __nv_bfloat16 yh = __float2bfloat16(y);
      __nv_bfloat16 yl = __float2bfloat16(y - __bfloat162float(yh));
      if (isQ) { d_QVh[mOff + d] = yh; d_QVl[mOff + d] = yl; }
      else     { d_SVh[mOff + d] = yh; d_SVl[mOff + d] = yl; d_SVf[mOff + d] = y; }
      qacc += y * y;
    }
    s1 = blockReduceSum(s1, red);
    s2 = blockReduceSum(s2, red);
    if (isQ) {
      qacc = blockReduceSum(qacc, red);
      if (tid == 0) d_qn[mBase + t] = qacc;
    }
    float mu  = s1 * (1.0f / DOUT);
    float var = s2 * (1.0f / DOUT) - mu * mu;
    float inv = rsqrtf(var + 1e-5f);
    for (int d = tid; d < DOUT; d += 256) {
      float z = (kv[d] - mu) * inv * gamma[d] + beta[d];
      __nv_bfloat16 zh = __float2bfloat16(z);
      __nv_bfloat16 zl = __float2bfloat16(z - __bfloat162float(zh));
      if (isQ) { d_QKh[mOff + d] = zh; d_QKl[mOff + d] = zl; }
      else     { d_SKh[mOff + d] = zh; d_SKl[mOff + d] = zl; }
    }
    __syncthreads();   // kv reuse guard before next tuple overwrites
  }
}

// ---------------- kernel 5: softmax + Gram quadratic form + logits -----------
__global__ void finalize_k(const float* __restrict__ gt, const float* __restrict__ tw,
                           float* __restrict__ out) {
  extern __shared__ float sm[];
  float* Gs  = sm;              // 19600 floats (140x140 Gram of this class)
  float* e   = sm + 19600;      // 140
  float* red = sm + 19740;      // 32
  int q = blockIdx.x, c = blockIdx.y;
  int tid = threadIdx.x;
  const float* Gsrc = d_G + (size_t)c * 19600;
  for (int idx = tid * 4; idx < 19600; idx += blockDim.x * 4)
    *(float4*)&Gs[idx] = *(const float4*)&Gsrc[idx];
  const float scale = rsqrtf((float)DOUT);
  float dist = 0.f;
  __syncthreads();
  for (int t = 0; t < TLEN; t++) {
    int m = q * TLEN + t;
    const float* Srow = d_S  + (size_t)m * MSP + c * 140;
    const float* Wrow = d_Wm + (size_t)m * MSP + c * 140;
    float lmax = -INFINITY;
    for (int j = tid; j < 140; j += blockDim.x) {
      float v = Srow[j] * scale;
      e[j] = v;
      lmax = fmaxf(lmax, v);
    }
    float mx = blockReduceMax(lmax, red);
    float lsum = 0.f, lw = 0.f;
    for (int j = tid; j < 140; j += blockDim.x) {
      float ev = expf(e[j] - mx);
      e[j] = ev;
      lsum += ev;
      lw   += ev * Wrow[j];
    }
    float Z  = blockReduceSum(lsum, red);
    float TW = blockReduceSum(lw, red);
    float qp = 0.f;
    for (int jc = tid; jc < 140; jc += blockDim.x) {
      float h = 0.f;
      #pragma unroll 4
      for (int j = 0; j < 140; j++)
        h += Gs[j * 140 + jc] * e[j];
      qp += h * e[jc];
    }
    float Q2 = blockReduceSum(qp, red);
    float invZ = 1.0f / Z;
    dist += d_qn[m] - 2.f * TW * invZ + Q2 * invZ * invZ;
    __syncthreads();
  }
  if (tid == 0)
    out[q * WAY + c] = -(dist * (1.0f / TLEN)) * gt[0] * tw[0];
}

// ---------------- launcher ---------------------------------------------------
extern "C" void kernel_launch(void* const* d_in, const int* in_sizes, int n_in,
                              void* d_out, int out_size) {
  const float* support = (const float*)d_in[0];
  /* d_in[1] = support_labels: sorted & balanced; reference uses a reshape */
  const float* queries = (const float*)d_in[2];
  const float* kw    = (const float*)d_in[3];
  const float* kb    = (const float*)d_in[4];
  const float* vw    = (const float*)d_in[5];
  const float* vb    = (const float*)d_in[6];
  const float* gamma = (const float*)d_in[7];
  const float* beta  = (const float*)d_in[8];
  const float* gt    = (const float*)d_in[9];
  const float* tw    = (const float*)d_in[10];
  float* out = (float*)d_out;

  __nv_bfloat16 *Xh, *Xl, *Wth, *Wtl, *QKh, *QKl, *QVh, *QVl, *SKh, *SKl, *SVh, *SVl;
  float *P, *SVf, *S, *Wm, *G;
  cudaGetSymbolAddress((void**)&Xh,  d_Xh);
  cudaGetSymbolAddress((void**)&Xl,  d_Xl);
  cudaGetSymbolAddress((void**)&Wth, d_Wth);
  cudaGetSymbolAddress((void**)&Wtl, d_Wtl);
  cudaGetSymbolAddress((void**)&P,   d_P);
  cudaGetSymbolAddress((void**)&QKh, d_QKh);
  cudaGetSymbolAddress((void**)&QKl, d_QKl);
  cudaGetSymbolAddress((void**)&QVh, d_QVh);
  cudaGetSymbolAddress((void**)&QVl, d_QVl);
  cudaGetSymbolAddress((void**)&SKh, d_SKh);
  cudaGetSymbolAddress((void**)&SKl, d_SKl);
  cudaGetSymbolAddress((void**)&SVh, d_SVh);
  cudaGetSymbolAddress((void**)&SVl, d_SVl);
  cudaGetSymbolAddress((void**)&SVf, d_SVf);
  cudaGetSymbolAddress((void**)&S,   d_S);
  cudaGetSymbolAddress((void**)&Wm,  d_Wm);
  cudaGetSymbolAddress((void**)&G,   d_G);

  cudaFuncSetAttribute(gemm3_mma, cudaFuncAttributeMaxDynamicSharedMemorySize, GSMEM);
  cudaFuncSetAttribute(combine2, cudaFuncAttributeMaxDynamicSharedMemorySize, CSMEM);
  cudaFuncSetAttribute(finalize_k, cudaFuncAttributeMaxDynamicSharedMemorySize,
                       (19600 + 140 + 32) * 4);

  // launch index 0/1: frames + PE -> bf16 hi/lo
  prep_q<<<(RQ * FEAT + 255) / 256, 256>>>(queries);
  prep_s<<<((MTP - RQ) * FEAT + 255) / 256, 256>>>(support);
  // launch index 2: weights -> [4608, 2048] K-contiguous bf16 hi/lo
  split_w<<<dim3(FEAT / 32, DOUT / 32, 4), dim3(32, 8)>>>(kw, vw);
  // launch index 3 (ncu-captured): all 4 projection planes in ONE tensor GEMM
  gemm3_mma<<<dim3(MTP / 128, NTP / 128), 256, GSMEM>>>(Xh, Xl, Wth, Wtl, P, FEAT, NTP);
  // per-item tuple combine + LN + bf16 splits (queries + support in one grid)
  combine2<<<NQv + NSv, 256, CSMEM>>>(kb, vb, gamma, beta);
  // per-class value Gram matrices (fp32, tiny, batched over z)
  sgemm_nt_gram<<<dim3(3, 3, WAY), 256>>>(SVf, G, 140, 140, DOUT,
                                          (size_t)140 * DOUT, (size_t)19600);
  // scores + value-overlap tensor GEMMs: [14080,1152]x[768,1152]^T
  gemm3_mma<<<dim3(MQP / 128, MSP / 128), 256, GSMEM>>>(QKh, QKl, SKh, SKl, S,  DOUT, MSP);
  gemm3_mma<<<dim3(MQP / 128, MSP / 128), 256, GSMEM>>>(QVh, QVl, SVh, SVl, Wm, DOUT, MSP);
  // softmax + quadratic-form distance + logits
  finalize_k<<<dim3(NQv, WAY), 160, (19600 + 140 + 32) * 4>>>(gt, tw, out);
}

// round 8
// speedup vs baseline: 2.3580x; 2.3580x over previous
#include <cuda_runtime.h>
#include <cuda_fp16.h>
#include <cstdint>
#include <math.h>

#define SEQ   8
#define FEAT  2048
#define DOUT  1152
#define TLEN  28
#define WAY   5
#define SHOT  5
#define NQv   500
#define NSv   25
#define RQ    (NQv*SEQ)     /* 4000 query frame rows   */
#define RS    (NSv*SEQ)     /* 200 support frame rows  */
#define RALL  (RQ+RS)       /* 4200                    */
#define MQ    (NQv*TLEN)    /* 14000 query tuples      */
#define MS    (NSv*TLEN)    /* 700 support tuples      */

// padded dims (multiples of 128 for the tensor GEMM; no bounds checks needed)
#define MTP   4224          /* padded frame rows                  */
#define NTP   4608          /* 4 planes x 1152 output cols        */
#define MQP   14080         /* padded query tuples                */
#define MSP   768           /* padded support tuples              */

// ---------------- scratch (static device memory; no allocations) -------------
// (zero-initialized at module load; padded rows are never written -> stay 0)
__device__ __half  d_X  [MTP*FEAT];
__device__ __half  d_Wt [NTP*FEAT];
__device__ float   d_P  [(size_t)MTP*NTP];   // 4-plane frame projections
__device__ __half  d_QK [(size_t)MQP*DOUT];
__device__ __half  d_QV [(size_t)MQP*DOUT];
__device__ __half  d_SK [(size_t)MSP*DOUT];
__device__ __half  d_SV [(size_t)MSP*DOUT];
__device__ float   d_SVf[(size_t)MSP*DOUT];
__device__ float   d_S  [(size_t)MQP*MSP];
__device__ float   d_Wm [(size_t)MQP*MSP];
__device__ float   d_qn [MQ];
__device__ float   d_G  [WAY*140*140];

__constant__ int c_tup[TLEN*2] = {
  0,1, 0,2, 0,3, 0,4, 0,5, 0,6, 0,7,
  1,2, 1,3, 1,4, 1,5, 1,6, 1,7,
  2,3, 2,4, 2,5, 2,6, 2,7,
  3,4, 3,5, 3,6, 3,7,
  4,5, 4,6, 4,7,
  5,6, 5,7,
  6,7
};

// ======================= generic-target helpers ==============================
__device__ __forceinline__ uint32_t smem_u32(const void* p) {
  uint32_t a;
  asm("{ .reg .u64 t; cvta.to.shared.u64 t, %1; cvt.u32.u64 %0, t; }" : "=r"(a) : "l"(p));
  return a;
}
__device__ __forceinline__ void ldsm4(uint32_t& r0, uint32_t& r1, uint32_t& r2,
                                      uint32_t& r3, uint32_t a) {
  asm volatile("ldmatrix.sync.aligned.m8n8.x4.shared.b16 {%0,%1,%2,%3}, [%4];"
               : "=r"(r0), "=r"(r1), "=r"(r2), "=r"(r3) : "r"(a));
}
__device__ __forceinline__ void mma_f16(float* c, const uint32_t* a, const uint32_t* b) {
  asm volatile("mma.sync.aligned.m16n8k16.row.col.f32.f16.f16.f32 "
               "{%0,%1,%2,%3}, {%4,%5,%6,%7}, {%8,%9}, {%0,%1,%2,%3};"
               : "+f"(c[0]), "+f"(c[1]), "+f"(c[2]), "+f"(c[3])
               : "r"(a[0]), "r"(a[1]), "r"(a[2]), "r"(a[3]), "r"(b[0]), "r"(b[1]));
}

// ======================= fp16 HMMA GEMM (single product) =====================
// C[M,N] = A[M,K] * B[N,K]^T   (K-contiguous, dims multiples of 128,
// K multiple of 64; fp32 C)
#define STAGES  3
#define TILE_B  16384                 /* 128 rows x 64 fp16 (128B rows) */
#define STAGE_B (2*TILE_B)            /* A tile + B tile = 32KB */
#define GSMEM   (STAGES*STAGE_B)      /* 96 KB -> 2 CTAs/SM */

__device__ __forceinline__ void load_stage(
    const __half* __restrict__ A, const __half* __restrict__ B,
    uint32_t stage, int m0, int n0, int k0, int K, int tid)
{
  #pragma unroll
  for (int i = 0; i < 8; i++) {
    int id   = tid + i * 256;
    int tile = id >> 10;                      // 0:A 1:B
    int row  = (id >> 3) & 127;
    int c16  = id & 7;                        // 16B chunk within 128B row
    const __half* base = (tile == 0) ? A : B;
    int r = ((tile == 0) ? m0 : n0) + row;
    const __half* src = base + (size_t)r * K + k0 + c16 * 8;
    uint32_t dst = stage + tile * TILE_B + (row << 7) + ((c16 ^ (row & 7)) << 4);
    asm volatile("cp.async.cg.shared.global [%0], [%1], 16;" :: "r"(dst), "l"(src) : "memory");
  }
  asm volatile("cp.async.commit_group;" ::: "memory");
}

__global__ void __launch_bounds__(256, 2)
gemm_f16(const __half* __restrict__ A, const __half* __restrict__ B,
         float* __restrict__ C, int K, int ldc)
{
  extern __shared__ char smem[];
  const uint32_t sb = smem_u32(smem);
  const int tid  = threadIdx.x;
  const int lane = tid & 31;
  const int wid  = tid >> 5;
  const int wm   = wid & 1;           // 2 m-blocks of 64
  const int wn   = wid >> 1;          // 4 n-blocks of 32
  const int m0 = blockIdx.x * 128, n0 = blockIdx.y * 128;
  const int NC = K >> 6;

  // ldmatrix per-lane addressing components
  const int q     = lane >> 3;
  const int lrow  = (q & 1) * 8 + (lane & 7);
  const int khalf = q >> 1;

  float acc[4][4][4];
  #pragma unroll
  for (int a = 0; a < 4; a++)
    #pragma unroll
    for (int b = 0; b < 4; b++)
      #pragma unroll
      for (int d = 0; d < 4; d++) acc[a][b][d] = 0.f;

  load_stage(A, B, sb + 0 * STAGE_B, m0, n0, 0,  K, tid);
  load_stage(A, B, sb + 1 * STAGE_B, m0, n0, 64, K, tid);

  for (int c = 0; c < NC; c++) {
    asm volatile("cp.async.wait_group 1;" ::: "memory");
    __syncthreads();
    if (c + 2 < NC)
      load_stage(A, B, sb + ((c + 2) % STAGES) * STAGE_B,
                 m0, n0, (c + 2) * 64, K, tid);
    else
      asm volatile("cp.async.commit_group;" ::: "memory");   // keep group count uniform

    const uint32_t st = sb + (c % STAGES) * STAGE_B;
    #pragma unroll
    for (int ks = 0; ks < 4; ks++) {
      const int cc = 2 * ks + khalf;
      uint32_t af[4][4];
      #pragma unroll
      for (int mi = 0; mi < 4; mi++) {
        int r = wm * 64 + mi * 16 + lrow;
        uint32_t ad = st + (r << 7) + ((cc ^ (r & 7)) << 4);
        ldsm4(af[mi][0], af[mi][1], af[mi][2], af[mi][3], ad);
      }
      uint32_t bf[4][2];
      #pragma unroll
      for (int g = 0; g < 2; g++) {
        int r = wn * 32 + g * 16 + lrow;
        uint32_t bd = st + TILE_B + (r << 7) + ((cc ^ (r & 7)) << 4);
        uint32_t t0, t1, t2, t3;
        ldsm4(t0, t1, t2, t3, bd);
        bf[2*g][0] = t0; bf[2*g][1] = t2; bf[2*g+1][0] = t1; bf[2*g+1][1] = t3;
      }
      #pragma unroll
      for (int mi = 0; mi < 4; mi++)
        #pragma unroll
        for (int nj = 0; nj < 4; nj++)
          mma_f16(acc[mi][nj], af[mi], bf[nj]);
    }
  }

  // epilogue: fragment -> C
  #pragma unroll
  for (int mi = 0; mi < 4; mi++) {
    int r = m0 + wm * 64 + mi * 16 + (lane >> 2);
    #pragma unroll
    for (int nj = 0; nj < 4; nj++) {
      int col = n0 + wn * 32 + nj * 8 + ((lane & 3) << 1);
      *(float2*)&C[(size_t)r * ldc + col]       = make_float2(acc[mi][nj][0], acc[mi][nj][1]);
      *(float2*)&C[(size_t)(r + 8) * ldc + col] = make_float2(acc[mi][nj][2], acc[mi][nj][3]);
    }
  }
}

// ---------------- reductions -------------------------------------------------
__device__ __forceinline__ float warpReduceSum(float v) {
  #pragma unroll
  for (int o = 16; o; o >>= 1) v += __shfl_xor_sync(0xffffffffu, v, o);
  return v;
}
__device__ __forceinline__ float warpReduceMax(float v) {
  #pragma unroll
  for (int o = 16; o; o >>= 1) v = fmaxf(v, __shfl_xor_sync(0xffffffffu, v, o));
  return v;
}
__device__ float blockReduceSum(float v, float* red) {
  int lane = threadIdx.x & 31, w = threadIdx.x >> 5;
  int nw = (blockDim.x + 31) >> 5;
  v = warpReduceSum(v);
  __syncthreads();
  if (lane == 0) red[w] = v;
  __syncthreads();
  if (w == 0) {
    float r = (lane < nw) ? red[lane] : 0.f;
    r = warpReduceSum(r);
    if (lane == 0) red[0] = r;
  }
  __syncthreads();
  return red[0];
}
__device__ float blockReduceMax(float v, float* red) {
  int lane = threadIdx.x & 31, w = threadIdx.x >> 5;
  int nw = (blockDim.x + 31) >> 5;
  v = warpReduceMax(v);
  __syncthreads();
  if (lane == 0) red[w] = v;
  __syncthreads();
  if (w == 0) {
    float r = (lane < nw) ? red[lane] : -INFINITY;
    r = warpReduceMax(r);
    if (lane == 0) red[0] = r;
  }
  __syncthreads();
  return red[0];
}

// ---------------- kernels 1a/1b: frames + PE -> fp16 -------------------------
__device__ __forceinline__ void prep_one(int idx, float v) {
  int d  = idx & (FEAT - 1);
  int r  = idx >> 11;
  int fr = r & 7;
  float freq = expf((float)(d & ~1) * (-9.210340371976184f / 2048.0f));
  float ang  = (float)fr * freq;
  float pe   = (d & 1) ? cosf(ang) : sinf(ang);
  d_X[idx] = __float2half(v + pe);
}
__global__ void prep_q(const float* __restrict__ q) {
  int idx = blockIdx.x * blockDim.x + threadIdx.x;
  if (idx >= RQ * FEAT) return;
  prep_one(idx, q[idx]);
}
__global__ void prep_s(const float* __restrict__ s) {
  int idx = blockIdx.x * blockDim.x + threadIdx.x;
  if (idx >= (MTP - RQ) * FEAT) return;
  int gidx = idx + RQ * FEAT;
  if (idx >= RS * FEAT) {                    // pad rows -> zeros
    d_X[gidx] = __float2half(0.f);
    return;
  }
  prep_one(gidx, s[idx]);
}

// ---------------- kernel 2: transpose weights into [NTP, FEAT] fp16 ----------
// z = plane: 0,1 from kw ; 2,3 from vw
__global__ void split_w(const float* __restrict__ kw, const float* __restrict__ vw) {
  __shared__ float tile[32][33];
  int p = blockIdx.z;
  const float* w = (p < 2) ? kw : vw;
  int k0 = blockIdx.x * 32, c0 = blockIdx.y * 32;
  int rbase = (p & 1) * FEAT;
  int tx = threadIdx.x, ty = threadIdx.y;  // 32 x 8
  #pragma unroll
  for (int i = 0; i < 32; i += 8)
    tile[ty + i][tx] = w[(size_t)(rbase + k0 + ty + i) * DOUT + c0 + tx];
  __syncthreads();
  #pragma unroll
  for (int i = 0; i < 32; i += 8) {
    size_t o = (size_t)(p * DOUT + c0 + ty + i) * FEAT + k0 + tx;
    d_Wt[o] = __float2half(tile[tx][ty + i]);
  }
}

// ---------------- kernel 3: fp32 sgemm, batched over z (Gram only) -----------
#define BM 64
#define BN 64
#define BK 16
__global__ void __launch_bounds__(256)
sgemm_nt_gram(const float* __restrict__ Abase, float* __restrict__ Cbase,
              int M, int N, int K, size_t strideA, size_t strideC) {
  const float* A = Abase + blockIdx.z * strideA;
  const float* B = A;
  float* C = Cbase + blockIdx.z * strideC;
  __shared__ __align__(16) float As[BK][BM + 4];
  __shared__ __align__(16) float Bs[BK][BN + 4];
  int tid = threadIdx.x;
  int tx = tid & 15, ty = tid >> 4;
  int m0 = blockIdx.x * BM, n0 = blockIdx.y * BN;
  int lr = tid >> 2;
  int lc = (tid & 3) << 2;
  float acc[4][4] = {};
  const float* Aptr = A + (size_t)(m0 + lr) * K + lc;
  const float* Bptr = B + (size_t)(n0 + lr) * K + lc;
  bool am = (m0 + lr) < M;
  bool bn = (n0 + lr) < N;
  for (int k0 = 0; k0 < K; k0 += BK) {
    float4 av = am ? *(const float4*)(Aptr + k0) : make_float4(0, 0, 0, 0);
    float4 bv = bn ? *(const float4*)(Bptr + k0) : make_float4(0, 0, 0, 0);
    As[lc + 0][lr] = av.x; As[lc + 1][lr] = av.y;
    As[lc + 2][lr] = av.z; As[lc + 3][lr] = av.w;
    Bs[lc + 0][lr] = bv.x; Bs[lc + 1][lr] = bv.y;
    Bs[lc + 2][lr] = bv.z; Bs[lc + 3][lr] = bv.w;
    __syncthreads();
    #pragma unroll
    for (int k = 0; k < BK; k++) {
      float4 a4 = *(const float4*)&As[k][ty << 2];
      float4 b4 = *(const float4*)&Bs[k][tx << 2];
      float ar[4] = {a4.x, a4.y, a4.z, a4.w};
      float br[4] = {b4.x, b4.y, b4.z, b4.w};
      #pragma unroll
      for (int i = 0; i < 4; i++)
        #pragma unroll
        for (int j = 0; j < 4; j++)
          acc[i][j] += ar[i] * br[j];
    }
    __syncthreads();
  }
  #pragma unroll
  for (int i = 0; i < 4; i++) {
    int m = m0 + (ty << 2) + i;
    if (m >= M) continue;
    #pragma unroll
    for (int j = 0; j < 4; j++) {
      int n = n0 + (tx << 2) + j;
      if (n < N) C[(size_t)m * N + n] = acc[i][j];
    }
  }
}

// ---------------- kernel 4: per-item tuple combine + LN(K) -> fp16 -----------
// One block per clip (525 total). Loads the clip's 8 frame-rows of d_P (all 4
// planes, 147 KB) into smem ONCE, then emits all 28 tuples from smem.
#define CSMEM ((8*NTP + DOUT + 32) * 4)
__global__ void __launch_bounds__(256)
combine2(const float* __restrict__ kb, const float* __restrict__ vb,
         const float* __restrict__ gamma, const float* __restrict__ beta) {
  extern __shared__ float cs[];
  float* sP  = cs;                 // 8 * 4608
  float* kv  = cs + 8 * NTP;       // 1152
  float* red = kv + DOUT;          // 32
  const int item = blockIdx.x;
  const bool isQ = item < NQv;
  const int tid = threadIdx.x;
  const float* src = d_P + (size_t)item * SEQ * NTP;
  for (int i = tid * 4; i < SEQ * NTP; i += 256 * 4)
    *(float4*)&sP[i] = *(const float4*)&src[i];
  __syncthreads();
  const int mBase = isQ ? item * TLEN : (item - NQv) * TLEN;
  for (int t = 0; t < TLEN; t++) {
    int fi = c_tup[2 * t], fj = c_tup[2 * t + 1];
    const float* pA = sP + fi * NTP;
    const float* pB = sP + fj * NTP;
    size_t mOff = (size_t)(mBase + t) * DOUT;
    float s1 = 0.f, s2 = 0.f, qacc = 0.f;
    for (int d = tid; d < DOUT; d += 256) {
      float x = pA[d] + pB[DOUT + d] + kb[d];
      kv[d] = x; s1 += x; s2 += x * x;
      float y = pA[2 * DOUT + d] + pB[3 * DOUT + d] + vb[d];
      if (isQ) { d_QV[mOff + d] = __float2half(y); }
      else     { d_SV[mOff + d] = __float2half(y); d_SVf[mOff + d] = y; }
      qacc += y * y;
    }
    s1 = blockReduceSum(s1, red);
    s2 = blockReduceSum(s2, red);
    if (isQ) {
      qacc = blockReduceSum(qacc, red);
      if (tid == 0) d_qn[mBase + t] = qacc;
    }
    float mu  = s1 * (1.0f / DOUT);
    float var = s2 * (1.0f / DOUT) - mu * mu;
    float inv = rsqrtf(var + 1e-5f);
    for (int d = tid; d < DOUT; d += 256) {
      float z = (kv[d] - mu) * inv * gamma[d] + beta[d];
      if (isQ) d_QK[mOff + d] = __float2half(z);
      else     d_SK[mOff + d] = __float2half(z);
    }
    __syncthreads();   // kv reuse guard before next tuple overwrites
  }
}

// ---------------- kernel 5: softmax + Gram quadratic form + logits -----------
__global__ void finalize_k(const float* __restrict__ gt, const float* __restrict__ tw,
                           float* __restrict__ out) {
  extern __shared__ float sm[];
  float* Gs  = sm;              // 19600 floats (140x140 Gram of this class)
  float* e   = sm + 19600;      // 140
  float* red = sm + 19740;      // 32
  int q = blockIdx.x, c = blockIdx.y;
  int tid = threadIdx.x;
  const float* Gsrc = d_G + (size_t)c * 19600;
  for (int idx = tid * 4; idx < 19600; idx += blockDim.x * 4)
    *(float4*)&Gs[idx] = *(const float4*)&Gsrc[idx];
  const float scale = rsqrtf((float)DOUT);
  float dist = 0.f;
  __syncthreads();
  for (int t = 0; t < TLEN; t++) {
    int m = q * TLEN + t;
    const float* Srow = d_S  + (size_t)m * MSP + c * 140;
    const float* Wrow = d_Wm + (size_t)m * MSP + c * 140;
    float lmax = -INFINITY;
    for (int j = tid; j < 140; j += blockDim.x) {
      float v = Srow[j] * scale;
      e[j] = v;
      lmax = fmaxf(lmax, v);
    }
    float mx = blockReduceMax(lmax, red);
    float lsum = 0.f, lw = 0.f;
    for (int j = tid; j < 140; j += blockDim.x) {
      float ev = expf(e[j] - mx);
      e[j] = ev;
      lsum += ev;
      lw   += ev * Wrow[j];
    }
    float Z  = blockReduceSum(lsum, red);
    float TW = blockReduceSum(lw, red);
    float qp = 0.f;
    for (int jc = tid; jc < 140; jc += blockDim.x) {
      float h = 0.f;
      #pragma unroll 4
      for (int j = 0; j < 140; j++)
        h += Gs[j * 140 + jc] * e[j];
      qp += h * e[jc];
    }
    float Q2 = blockReduceSum(qp, red);
    float invZ = 1.0f / Z;
    dist += d_qn[m] - 2.f * TW * invZ + Q2 * invZ * invZ;
    __syncthreads();
  }
  if (tid == 0)
    out[q * WAY + c] = -(dist * (1.0f / TLEN)) * gt[0] * tw[0];
}

// ---------------- launcher ---------------------------------------------------
extern "C" void kernel_launch(void* const* d_in, const int* in_sizes, int n_in,
                              void* d_out, int out_size) {
  const float* support = (const float*)d_in[0];
  /* d_in[1] = support_labels: sorted & balanced; reference uses a reshape */
  const float* queries = (const float*)d_in[2];
  const float* kw    = (const float*)d_in[3];
  const float* kb    = (const float*)d_in[4];
  const float* vw    = (const float*)d_in[5];
  const float* vb    = (const float*)d_in[6];
  const float* gamma = (const float*)d_in[7];
  const float* beta  = (const float*)d_in[8];
  const float* gt    = (const float*)d_in[9];
  const float* tw    = (const float*)d_in[10];
  float* out = (float*)d_out;

  __half *X, *Wt, *QK, *QV, *SK, *SV;
  float *P, *SVf, *S, *Wm, *G;
  cudaGetSymbolAddress((void**)&X,   d_X);
  cudaGetSymbolAddress((void**)&Wt,  d_Wt);
  cudaGetSymbolAddress((void**)&P,   d_P);
  cudaGetSymbolAddress((void**)&QK,  d_QK);
  cudaGetSymbolAddress((void**)&QV,  d_QV);
  cudaGetSymbolAddress((void**)&SK,  d_SK);
  cudaGetSymbolAddress((void**)&SV,  d_SV);
  cudaGetSymbolAddress((void**)&SVf, d_SVf);
  cudaGetSymbolAddress((void**)&S,   d_S);
  cudaGetSymbolAddress((void**)&Wm,  d_Wm);
  cudaGetSymbolAddress((void**)&G,   d_G);

  cudaFuncSetAttribute(gemm_f16, cudaFuncAttributeMaxDynamicSharedMemorySize, GSMEM);
  cudaFuncSetAttribute(combine2, cudaFuncAttributeMaxDynamicSharedMemorySize, CSMEM);
  cudaFuncSetAttribute(finalize_k, cudaFuncAttributeMaxDynamicSharedMemorySize,
                       (19600 + 140 + 32) * 4);

  // launch index 0/1: frames + PE -> fp16
  prep_q<<<(RQ * FEAT + 255) / 256, 256>>>(queries);
  prep_s<<<((MTP - RQ) * FEAT + 255) / 256, 256>>>(support);
  // launch index 2: weights -> [4608, 2048] K-contiguous fp16
  split_w<<<dim3(FEAT / 32, DOUT / 32, 4), dim3(32, 8)>>>(kw, vw);
  // launch index 3 (ncu-captured): all 4 projection planes in ONE fp16 GEMM
  gemm_f16<<<dim3(MTP / 128, NTP / 128), 256, GSMEM>>>(X, Wt, P, FEAT, NTP);
  // per-item tuple combine + LN + fp16 casts (queries + support in one grid)
  combine2<<<NQv + NSv, 256, CSMEM>>>(kb, vb, gamma, beta);
  // per-class value Gram matrices (fp32, tiny, batched over z)
  sgemm_nt_gram<<<dim3(3, 3, WAY), 256>>>(SVf, G, 140, 140, DOUT,
                                          (size_t)140 * DOUT, (size_t)19600);
  // scores + value-overlap fp16 GEMMs: [14080,1152]x[768,1152]^T
  gemm_f16<<<dim3(MQP / 128, MSP / 128), 256, GSMEM>>>(QK, SK, S,  DOUT, MSP);
  gemm_f16<<<dim3(MQP / 128, MSP / 128), 256, GSMEM>>>(QV, SV, Wm, DOUT, MSP);
  // softmax + quadratic-form distance + logits
  finalize_k<<<dim3(NQv, WAY), 160, (19600 + 140 + 32) * 4>>>(gt, tw, out);
}

// round 9
// speedup vs baseline: 5.5039x; 2.3341x over previous
#include <cuda_runtime.h>
#include <cuda_fp16.h>
#include <cstdint>
#include <math.h>

#define SEQ   8
#define FEAT  2048
#define DOUT  1152
#define TLEN  28
#define WAY   5
#define SHOT  5
#define NQv   500
#define NSv   25
#define RQ    (NQv*SEQ)     /* 4000 query frame rows   */
#define RS    (NSv*SEQ)     /* 200 support frame rows  */
#define RALL  (RQ+RS)       /* 4200                    */
#define MQ    (NQv*TLEN)    /* 14000 query tuples      */
#define MS    (NSv*TLEN)    /* 700 support tuples      */

// padded dims (multiples of 128 for the tensor GEMM; no bounds checks needed)
#define MTP   4224          /* padded frame rows                  */
#define NTP   4608          /* 4 planes x 1152 output cols        */
#define MQP   14080         /* padded query tuples                */
#define MSP   768           /* padded support tuples              */

// ---------------- scratch (static device memory; no allocations) -------------
__device__ float   d_PE [SEQ*FEAT];          // positional encoding table
__device__ __half  d_X  [MTP*FEAT];
__device__ __half  d_Wt [NTP*FEAT];
__device__ float   d_P  [(size_t)MTP*NTP];   // 4-plane frame projections
__device__ __half  d_QK [(size_t)MQP*DOUT];
__device__ __half  d_QV [(size_t)MQP*DOUT];
__device__ __half  d_SK [(size_t)MSP*DOUT];
__device__ __half  d_SV [(size_t)MSP*DOUT];
__device__ float   d_SVf[(size_t)MSP*DOUT];
__device__ float   d_S  [(size_t)MQP*MSP];
__device__ float   d_Wm [(size_t)MQP*MSP];
__device__ float   d_qn [MQ];
__device__ float   d_G  [WAY*140*140];

__constant__ int c_tup[TLEN*2] = {
  0,1, 0,2, 0,3, 0,4, 0,5, 0,6, 0,7,
  1,2, 1,3, 1,4, 1,5, 1,6, 1,7,
  2,3, 2,4, 2,5, 2,6, 2,7,
  3,4, 3,5, 3,6, 3,7,
  4,5, 4,6, 4,7,
  5,6, 5,7,
  6,7
};

// ======================= generic-target helpers ==============================
__device__ __forceinline__ uint32_t smem_u32(const void* p) {
  uint32_t a;
  asm("{ .reg .u64 t; cvta.to.shared.u64 t, %1; cvt.u32.u64 %0, t; }" : "=r"(a) : "l"(p));
  return a;
}
__device__ __forceinline__ void ldsm4(uint32_t& r0, uint32_t& r1, uint32_t& r2,
                                      uint32_t& r3, uint32_t a) {
  asm volatile("ldmatrix.sync.aligned.m8n8.x4.shared.b16 {%0,%1,%2,%3}, [%4];"
               : "=r"(r0), "=r"(r1), "=r"(r2), "=r"(r3) : "r"(a));
}
__device__ __forceinline__ void mma_f16(float* c, const uint32_t* a, const uint32_t* b) {
  asm volatile("mma.sync.aligned.m16n8k16.row.col.f32.f16.f16.f32 "
               "{%0,%1,%2,%3}, {%4,%5,%6,%7}, {%8,%9}, {%0,%1,%2,%3};"
               : "+f"(c[0]), "+f"(c[1]), "+f"(c[2]), "+f"(c[3])
               : "r"(a[0]), "r"(a[1]), "r"(a[2]), "r"(a[3]), "r"(b[0]), "r"(b[1]));
}
__device__ __forceinline__ float warpReduceSum(float v) {
  #pragma unroll
  for (int o = 16; o; o >>= 1) v += __shfl_xor_sync(0xffffffffu, v, o);
  return v;
}
__device__ __forceinline__ float warpReduceMax(float v) {
  #pragma unroll
  for (int o = 16; o; o >>= 1) v = fmaxf(v, __shfl_xor_sync(0xffffffffu, v, o));
  return v;
}

// ======================= fp16 HMMA GEMM (single product) =====================
// C[M,N] = A[M,K] * B[N,K]^T   (K-contiguous, dims multiples of 128,
// K multiple of 64; fp32 C)
#define STAGES  3
#define TILE_B  16384                 /* 128 rows x 64 fp16 (128B rows) */
#define STAGE_B (2*TILE_B)            /* A tile + B tile = 32KB */
#define GSMEM   (STAGES*STAGE_B)      /* 96 KB -> 2 CTAs/SM */

__device__ __forceinline__ void load_stage(
    const __half* __restrict__ A, const __half* __restrict__ B,
    uint32_t stage, int m0, int n0, int k0, int K, int tid)
{
  #pragma unroll
  for (int i = 0; i < 8; i++) {
    int id   = tid + i * 256;
    int tile = id >> 10;                      // 0:A 1:B
    int row  = (id >> 3) & 127;
    int c16  = id & 7;                        // 16B chunk within 128B row
    const __half* base = (tile == 0) ? A : B;
    int r = ((tile == 0) ? m0 : n0) + row;
    const __half* src = base + (size_t)r * K + k0 + c16 * 8;
    uint32_t dst = stage + tile * TILE_B + (row << 7) + ((c16 ^ (row & 7)) << 4);
    asm volatile("cp.async.cg.shared.global [%0], [%1], 16;" :: "r"(dst), "l"(src) : "memory");
  }
  asm volatile("cp.async.commit_group;" ::: "memory");
}

__global__ void __launch_bounds__(256, 2)
gemm_f16(const __half* __restrict__ A, const __half* __restrict__ B,
         float* __restrict__ C, int K, int ldc)
{
  extern __shared__ char smem[];
  const uint32_t sb = smem_u32(smem);
  const int tid  = threadIdx.x;
  const int lane = tid & 31;
  const int wid  = tid >> 5;
  const int wm   = wid & 1;           // 2 m-blocks of 64
  const int wn   = wid >> 1;          // 4 n-blocks of 32
  const int m0 = blockIdx.x * 128, n0 = blockIdx.y * 128;
  const int NC = K >> 6;

  const int q     = lane >> 3;
  const int lrow  = (q & 1) * 8 + (lane & 7);
  const int khalf = q >> 1;

  float acc[4][4][4];
  #pragma unroll
  for (int a = 0; a < 4; a++)
    #pragma unroll
    for (int b = 0; b < 4; b++)
      #pragma unroll
      for (int d = 0; d < 4; d++) acc[a][b][d] = 0.f;

  load_stage(A, B, sb + 0 * STAGE_B, m0, n0, 0,  K, tid);
  load_stage(A, B, sb + 1 * STAGE_B, m0, n0, 64, K, tid);

  for (int c = 0; c < NC; c++) {
    asm volatile("cp.async.wait_group 1;" ::: "memory");
    __syncthreads();
    if (c + 2 < NC)
      load_stage(A, B, sb + ((c + 2) % STAGES) * STAGE_B,
                 m0, n0, (c + 2) * 64, K, tid);
    else
      asm volatile("cp.async.commit_group;" ::: "memory");   // keep group count uniform

    const uint32_t st = sb + (c % STAGES) * STAGE_B;
    #pragma unroll
    for (int ks = 0; ks < 4; ks++) {
      const int cc = 2 * ks + khalf;
      uint32_t af[4][4];
      #pragma unroll
      for (int mi = 0; mi < 4; mi++) {
        int r = wm * 64 + mi * 16 + lrow;
        uint32_t ad = st + (r << 7) + ((cc ^ (r & 7)) << 4);
        ldsm4(af[mi][0], af[mi][1], af[mi][2], af[mi][3], ad);
      }
      uint32_t bf[4][2];
      #pragma unroll
      for (int g = 0; g < 2; g++) {
        int r = wn * 32 + g * 16 + lrow;
        uint32_t bd = st + TILE_B + (r << 7) + ((cc ^ (r & 7)) << 4);
        uint32_t t0, t1, t2, t3;
        ldsm4(t0, t1, t2, t3, bd);
        bf[2*g][0] = t0; bf[2*g][1] = t2; bf[2*g+1][0] = t1; bf[2*g+1][1] = t3;
      }
      #pragma unroll
      for (int mi = 0; mi < 4; mi++)
        #pragma unroll
        for (int nj = 0; nj < 4; nj++)
          mma_f16(acc[mi][nj], af[mi], bf[nj]);
    }
  }

  #pragma unroll
  for (int mi = 0; mi < 4; mi++) {
    int r = m0 + wm * 64 + mi * 16 + (lane >> 2);
    #pragma unroll
    for (int nj = 0; nj < 4; nj++) {
      int col = n0 + wn * 32 + nj * 8 + ((lane & 3) << 1);
      *(float2*)&C[(size_t)r * ldc + col]       = make_float2(acc[mi][nj][0], acc[mi][nj][1]);
      *(float2*)&C[(size_t)(r + 8) * ldc + col] = make_float2(acc[mi][nj][2], acc[mi][nj][3]);
    }
  }
}

// ---------------- kernel 0: positional-encoding table (16K elems) ------------
__global__ void pe_build() {
  int idx = blockIdx.x * blockDim.x + threadIdx.x;
  if (idx >= SEQ * FEAT) return;
  int d  = idx & (FEAT - 1);
  int fr = idx >> 11;
  float freq = expf((float)(d & ~1) * (-9.210340371976184f / 2048.0f));
  float ang  = (float)fr * freq;
  d_PE[idx] = (d & 1) ? cosf(ang) : sinf(ang);
}

// ---------------- kernel 1: frames + PE -> fp16 (memory-bound) ---------------
__global__ void prep(const float* __restrict__ q, const float* __restrict__ s) {
  int idx = blockIdx.x * blockDim.x + threadIdx.x;
  if (idx >= MTP * FEAT) return;
  int r = idx >> 11;
  if (r >= RALL) { d_X[idx] = __float2half(0.f); return; }
  float v = (r < RQ) ? q[idx] : s[idx - (size_t)RQ * FEAT];
  d_X[idx] = __float2half(v + d_PE[idx & (SEQ * FEAT - 1)]);
}

// ---------------- kernel 2: transpose weights into [NTP, FEAT] fp16 ----------
__global__ void split_w(const float* __restrict__ kw, const float* __restrict__ vw) {
  __shared__ float tile[32][33];
  int p = blockIdx.z;
  const float* w = (p < 2) ? kw : vw;
  int k0 = blockIdx.x * 32, c0 = blockIdx.y * 32;
  int rbase = (p & 1) * FEAT;
  int tx = threadIdx.x, ty = threadIdx.y;  // 32 x 8
  #pragma unroll
  for (int i = 0; i < 32; i += 8)
    tile[ty + i][tx] = w[(size_t)(rbase + k0 + ty + i) * DOUT + c0 + tx];
  __syncthreads();
  #pragma unroll
  for (int i = 0; i < 32; i += 8) {
    size_t o = (size_t)(p * DOUT + c0 + ty + i) * FEAT + k0 + tx;
    d_Wt[o] = __float2half(tile[tx][ty + i]);
  }
}

// ---------------- kernel 3: fp32 sgemm, batched over z (Gram only) -----------
#define BM 64
#define BN 64
#define BK 16
__global__ void __launch_bounds__(256)
sgemm_nt_gram(const float* __restrict__ Abase, float* __restrict__ Cbase,
              int M, int N, int K, size_t strideA, size_t strideC) {
  const float* A = Abase + blockIdx.z * strideA;
  const float* B = A;
  float* C = Cbase + blockIdx.z * strideC;
  __shared__ __align__(16) float As[BK][BM + 4];
  __shared__ __align__(16) float Bs[BK][BN + 4];
  int tid = threadIdx.x;
  int tx = tid & 15, ty = tid >> 4;
  int m0 = blockIdx.x * BM, n0 = blockIdx.y * BN;
  int lr = tid >> 2;
  int lc = (tid & 3) << 2;
  float acc[4][4] = {};
  const float* Aptr = A + (size_t)(m0 + lr) * K + lc;
  const float* Bptr = B + (size_t)(n0 + lr) * K + lc;
  bool am = (m0 + lr) < M;
  bool bn = (n0 + lr) < N;
  for (int k0 = 0; k0 < K; k0 += BK) {
    float4 av = am ? *(const float4*)(Aptr + k0) : make_float4(0, 0, 0, 0);
    float4 bv = bn ? *(const float4*)(Bptr + k0) : make_float4(0, 0, 0, 0);
    As[lc + 0][lr] = av.x; As[lc + 1][lr] = av.y;
    As[lc + 2][lr] = av.z; As[lc + 3][lr] = av.w;
    Bs[lc + 0][lr] = bv.x; Bs[lc + 1][lr] = bv.y;
    Bs[lc + 2][lr] = bv.z; Bs[lc + 3][lr] = bv.w;
    __syncthreads();
    #pragma unroll
    for (int k = 0; k < BK; k++) {
      float4 a4 = *(const float4*)&As[k][ty << 2];
      float4 b4 = *(const float4*)&Bs[k][tx << 2];
      float ar[4] = {a4.x, a4.y, a4.z, a4.w};
      float br[4] = {b4.x, b4.y, b4.z, b4.w};
      #pragma unroll
      for (int i = 0; i < 4; i++)
        #pragma unroll
        for (int j = 0; j < 4; j++)
          acc[i][j] += ar[i] * br[j];
    }
    __syncthreads();
  }
  #pragma unroll
  for (int i = 0; i < 4; i++) {
    int m = m0 + (ty << 2) + i;
    if (m >= M) continue;
    #pragma unroll
    for (int j = 0; j < 4; j++) {
      int n = n0 + (tx << 2) + j;
      if (n < N) C[(size_t)m * N + n] = acc[i][j];
    }
  }
}

// ---------------- kernel 4: per-item combine, warp-parallel tuples -----------
// One block per clip. Loads the clip's 8 frame-rows of d_P into smem once;
// each warp owns whole tuples -> warp-shuffle reductions, no block syncs.
#define CSMEM (8*NTP*4)
__global__ void __launch_bounds__(256)
combine2(const float* __restrict__ kb, const float* __restrict__ vb,
         const float* __restrict__ gamma, const float* __restrict__ beta) {
  extern __shared__ float sP[];     // 8 * 4608 floats
  const int item = blockIdx.x;
  const bool isQ = item < NQv;
  const int tid = threadIdx.x;
  const int lane = tid & 31;
  const int w = tid >> 5;
  const float* src = d_P + (size_t)item * SEQ * NTP;
  for (int i = tid * 4; i < SEQ * NTP; i += 256 * 4)
    *(float4*)&sP[i] = *(const float4*)&src[i];
  __syncthreads();
  const int mBase = isQ ? item * TLEN : (item - NQv) * TLEN;
  for (int t = w; t < TLEN; t += 8) {
    const int fi = c_tup[2 * t], fj = c_tup[2 * t + 1];
    const float* pA = sP + fi * NTP;
    const float* pB = sP + fj * NTP;
    const size_t mOff = (size_t)(mBase + t) * DOUT;
    float xs[36];                   // DOUT = 36 * 32 exactly
    float s1 = 0.f, s2 = 0.f, qacc = 0.f;
    #pragma unroll
    for (int i = 0; i < 36; i++) {
      int d = lane + i * 32;
      float x = pA[d] + pB[DOUT + d] + kb[d];
      xs[i] = x; s1 += x; s2 += x * x;
      float y = pA[2 * DOUT + d] + pB[3 * DOUT + d] + vb[d];
      if (isQ) { d_QV[mOff + d] = __float2half(y); }
      else     { d_SV[mOff + d] = __float2half(y); d_SVf[mOff + d] = y; }
      qacc += y * y;
    }
    s1 = warpReduceSum(s1);
    s2 = warpReduceSum(s2);
    if (isQ) {
      qacc = warpReduceSum(qacc);
      if (lane == 0) d_qn[mBase + t] = qacc;
    }
    float mu  = s1 * (1.0f / DOUT);
    float var = s2 * (1.0f / DOUT) - mu * mu;
    float inv = rsqrtf(var + 1e-5f);
    #pragma unroll
    for (int i = 0; i < 36; i++) {
      int d = lane + i * 32;
      float z = (xs[i] - mu) * inv * gamma[d] + beta[d];
      if (isQ) d_QK[mOff + d] = __float2half(z);
      else     d_SK[mOff + d] = __float2half(z);
    }
  }
}

// ---------------- kernel 5: softmax + Gram quadratic form + logits -----------
// Block = (query q, class c), 256 threads. Warps 0..6 each own 4 tuples.
// Quadratic form register-blocked: per j, 5 Gram loads + 4 e loads feed 20 FMAs.
#define FSMEM ((19600 + TLEN*140 + 8) * 4)
__global__ void __launch_bounds__(256)
finalize_k(const float* __restrict__ gt, const float* __restrict__ tw,
           float* __restrict__ out) {
  extern __shared__ float sm[];
  float* Gs  = sm;                  // 19600
  float* es  = sm + 19600;          // 28 * 140 unnormalized softmax vectors
  float* red = es + TLEN * 140;     // 8
  const int qq = blockIdx.x, c = blockIdx.y;
  const int tid = threadIdx.x;
  const int lane = tid & 31;
  const int w = tid >> 5;
  const float* Gsrc = d_G + (size_t)c * 19600;
  for (int idx = tid * 4; idx < 19600; idx += 256 * 4)
    *(float4*)&Gs[idx] = *(const float4*)&Gsrc[idx];
  __syncthreads();

  float dist = 0.f;
  if (w < 7) {
    const float scale = rsqrtf((float)DOUT);
    const int t0 = w * 4;
    float Zs[4], TWs[4];
    // ---- phase 1: softmax stats for this warp's 4 tuples ----
    #pragma unroll
    for (int tt = 0; tt < 4; tt++) {
      const int m = qq * TLEN + t0 + tt;
      const float* Srow = d_S  + (size_t)m * MSP + c * 140;
      const float* Wrow = d_Wm + (size_t)m * MSP + c * 140;
      float ev[5];
      float lmax = -INFINITY;
      #pragma unroll
      for (int i = 0; i < 5; i++) {
        int j = lane + i * 32;
        if (j < 140) { ev[i] = Srow[j] * scale; lmax = fmaxf(lmax, ev[i]); }
        else ev[i] = -INFINITY;
      }
      lmax = warpReduceMax(lmax);
      float lsum = 0.f, lw = 0.f;
      #pragma unroll
      for (int i = 0; i < 5; i++) {
        int j = lane + i * 32;
        if (j < 140) {
          float e = __expf(ev[i] - lmax);
          es[(t0 + tt) * 140 + j] = e;
          lsum += e;
          lw   += e * Wrow[j];
        }
      }
      Zs[tt]  = warpReduceSum(lsum);
      TWs[tt] = warpReduceSum(lw);
    }
    __syncwarp();
    // ---- phase 2: quadratic forms for 4 tuples simultaneously ----
    float hq[5][4];
    #pragma unroll
    for (int i = 0; i < 5; i++)
      #pragma unroll
      for (int tt = 0; tt < 4; tt++) hq[i][tt] = 0.f;
    for (int j = 0; j < 140; j++) {
      float e4[4];
      #pragma unroll
      for (int tt = 0; tt < 4; tt++) e4[tt] = es[(t0 + tt) * 140 + j];
      const float* Grow = Gs + j * 140;
      #pragma unroll
      for (int i = 0; i < 5; i++) {
        int jc = lane + i * 32;
        float g = (jc < 140) ? Grow[jc] : 0.f;
        #pragma unroll
        for (int tt = 0; tt < 4; tt++) hq[i][tt] += g * e4[tt];
      }
    }
    #pragma unroll
    for (int tt = 0; tt < 4; tt++) {
      float qp = 0.f;
      #pragma unroll
      for (int i = 0; i < 5; i++) {
        int jc = lane + i * 32;
        if (jc < 140) qp += hq[i][tt] * es[(t0 + tt) * 140 + jc];
      }
      qp = warpReduceSum(qp);
      float invZ = 1.0f / Zs[tt];
      dist += d_qn[qq * TLEN + t0 + tt] - 2.f * TWs[tt] * invZ + qp * invZ * invZ;
    }
  }
  if (lane == 0) red[w] = dist;
  __syncthreads();
  if (tid == 0) {
    float s = 0.f;
    #pragma unroll
    for (int i = 0; i < 7; i++) s += red[i];
    out[qq * WAY + c] = -(s * (1.0f / TLEN)) * gt[0] * tw[0];
  }
}

// ---------------- launcher ---------------------------------------------------
extern "C" void kernel_launch(void* const* d_in, const int* in_sizes, int n_in,
                              void* d_out, int out_size) {
  const float* support = (const float*)d_in[0];
  /* d_in[1] = support_labels: sorted & balanced; reference uses a reshape */
  const float* queries = (const float*)d_in[2];
  const float* kw    = (const float*)d_in[3];
  const float* kb    = (const float*)d_in[4];
  const float* vw    = (const float*)d_in[5];
  const float* vb    = (const float*)d_in[6];
  const float* gamma = (const float*)d_in[7];
  const float* beta  = (const float*)d_in[8];
  const float* gt    = (const float*)d_in[9];
  const float* tw    = (const float*)d_in[10];
  float* out = (float*)d_out;

  __half *X, *Wt, *QK, *QV, *SK, *SV;
  float *P, *SVf, *S, *Wm, *G;
  cudaGetSymbolAddress((void**)&X,   d_X);
  cudaGetSymbolAddress((void**)&Wt,  d_Wt);
  cudaGetSymbolAddress((void**)&P,   d_P);
  cudaGetSymbolAddress((void**)&QK,  d_QK);
  cudaGetSymbolAddress((void**)&QV,  d_QV);
  cudaGetSymbolAddress((void**)&SK,  d_SK);
  cudaGetSymbolAddress((void**)&SV,  d_SV);
  cudaGetSymbolAddress((void**)&SVf, d_SVf);
  cudaGetSymbolAddress((void**)&S,   d_S);
  cudaGetSymbolAddress((void**)&Wm,  d_Wm);
  cudaGetSymbolAddress((void**)&G,   d_G);

  cudaFuncSetAttribute(gemm_f16, cudaFuncAttributeMaxDynamicSharedMemorySize, GSMEM);
  cudaFuncSetAttribute(combine2, cudaFuncAttributeMaxDynamicSharedMemorySize, CSMEM);
  cudaFuncSetAttribute(finalize_k, cudaFuncAttributeMaxDynamicSharedMemorySize, FSMEM);

  // launch 0: PE table (16K elems)
  pe_build<<<(SEQ * FEAT + 255) / 256, 256>>>();
  // launch 1: frames + PE -> fp16 (memory-bound)
  prep<<<(MTP * FEAT + 255) / 256, 256>>>(queries, support);
  // launch 2: weights -> [4608, 2048] K-contiguous fp16
  split_w<<<dim3(FEAT / 32, DOUT / 32, 4), dim3(32, 8)>>>(kw, vw);
  // launch 3 (ncu-captured): all 4 projection planes in ONE fp16 GEMM
  gemm_f16<<<dim3(MTP / 128, NTP / 128), 256, GSMEM>>>(X, Wt, P, FEAT, NTP);
  // per-item tuple combine + LN + fp16 casts (warp-parallel tuples)
  combine2<<<NQv + NSv, 256, CSMEM>>>(kb, vb, gamma, beta);
  // per-class value Gram matrices (fp32, tiny, batched over z)
  sgemm_nt_gram<<<dim3(3, 3, WAY), 256>>>(SVf, G, 140, 140, DOUT,
                                          (size_t)140 * DOUT, (size_t)19600);
  // scores + value-overlap fp16 GEMMs: [14080,1152]x[768,1152]^T
  gemm_f16<<<dim3(MQP / 128, MSP / 128), 256, GSMEM>>>(QK, SK, S,  DOUT, MSP);
  gemm_f16<<<dim3(MQP / 128, MSP / 128), 256, GSMEM>>>(QV, SV, Wm, DOUT, MSP);
  // softmax + quadratic-form distance + logits
  finalize_k<<<dim3(NQv, WAY), 256, FSMEM>>>(gt, tw, out);
}

// round 10
// speedup vs baseline: 5.6418x; 1.0251x over previous
#include <cuda_runtime.h>
#include <cuda_fp16.h>
#include <cstdint>
#include <math.h>

#define SEQ   8
#define FEAT  2048
#define DOUT  1152
#define TLEN  28
#define WAY   5
#define SHOT  5
#define NQv   500
#define NSv   25
#define RQ    (NQv*SEQ)     /* 4000 query frame rows   */
#define RS    (NSv*SEQ)     /* 200 support frame rows  */
#define RALL  (RQ+RS)       /* 4200                    */
#define MQ    (NQv*TLEN)    /* 14000 query tuples      */
#define MS    (NSv*TLEN)    /* 700 support tuples      */

// padded dims (multiples of 128 for the tensor GEMM; no bounds checks needed)
#define MTP   4224          /* padded frame rows                  */
#define NTP   4608          /* 4 planes x 1152 output cols        */
#define MQP   14080         /* padded query tuples                */
#define MSP   768           /* padded support tuples              */

// ---------------- scratch (static device memory; no allocations) -------------
__device__ float   d_PE [SEQ*FEAT];          // positional encoding table
__device__ __half  d_X  [MTP*FEAT];
__device__ __half  d_Wt [NTP*FEAT];
__device__ __half  d_P  [(size_t)MTP*NTP];   // 4-plane frame projections (fp16)
__device__ __half  d_QK [(size_t)MQP*DOUT];
__device__ __half  d_QV [(size_t)MQP*DOUT];
__device__ __half  d_SK [(size_t)MSP*DOUT];
__device__ __half  d_SV [(size_t)MSP*DOUT];
__device__ float   d_SVf[(size_t)MSP*DOUT];
__device__ float   d_S  [(size_t)MQP*MSP];
__device__ float   d_Wm [(size_t)MQP*MSP];
__device__ float   d_qn [MQ];
__device__ float   d_G  [WAY*140*140];

__constant__ int c_tup[TLEN*2] = {
  0,1, 0,2, 0,3, 0,4, 0,5, 0,6, 0,7,
  1,2, 1,3, 1,4, 1,5, 1,6, 1,7,
  2,3, 2,4, 2,5, 2,6, 2,7,
  3,4, 3,5, 3,6, 3,7,
  4,5, 4,6, 4,7,
  5,6, 5,7,
  6,7
};

// ======================= generic-target helpers ==============================
__device__ __forceinline__ uint32_t smem_u32(const void* p) {
  uint32_t a;
  asm("{ .reg .u64 t; cvta.to.shared.u64 t, %1; cvt.u32.u64 %0, t; }" : "=r"(a) : "l"(p));
  return a;
}
__device__ __forceinline__ void ldsm4(uint32_t& r0, uint32_t& r1, uint32_t& r2,
                                      uint32_t& r3, uint32_t a) {
  asm volatile("ldmatrix.sync.aligned.m8n8.x4.shared.b16 {%0,%1,%2,%3}, [%4];"
               : "=r"(r0), "=r"(r1), "=r"(r2), "=r"(r3) : "r"(a));
}
__device__ __forceinline__ void mma_f16(float* c, const uint32_t* a, const uint32_t* b) {
  asm volatile("mma.sync.aligned.m16n8k16.row.col.f32.f16.f16.f32 "
               "{%0,%1,%2,%3}, {%4,%5,%6,%7}, {%8,%9}, {%0,%1,%2,%3};"
               : "+f"(c[0]), "+f"(c[1]), "+f"(c[2]), "+f"(c[3])
               : "r"(a[0]), "r"(a[1]), "r"(a[2]), "r"(a[3]), "r"(b[0]), "r"(b[1]));
}
__device__ __forceinline__ float warpReduceSum(float v) {
  #pragma unroll
  for (int o = 16; o; o >>= 1) v += __shfl_xor_sync(0xffffffffu, v, o);
  return v;
}
__device__ __forceinline__ float warpReduceMax(float v) {
  #pragma unroll
  for (int o = 16; o; o >>= 1) v = fmaxf(v, __shfl_xor_sync(0xffffffffu, v, o));
  return v;
}

// ======================= fp16 HMMA GEMM (single product) =====================
// C[M,N] = A[M,K] * B[N,K]^T   (K-contiguous, dims multiples of 128,
// K multiple of 64); C is fp32 or fp16 (HALF_OUT template flag)
#define STAGES  3
#define TILE_B  16384                 /* 128 rows x 64 fp16 (128B rows) */
#define STAGE_B (2*TILE_B)            /* A tile + B tile = 32KB */
#define GSMEM   (STAGES*STAGE_B)      /* 96 KB -> 2 CTAs/SM */

__device__ __forceinline__ void load_stage(
    const __half* __restrict__ A, const __half* __restrict__ B,
    uint32_t stage, int m0, int n0, int k0, int K, int tid)
{
  #pragma unroll
  for (int i = 0; i < 8; i++) {
    int id   = tid + i * 256;
    int tile = id >> 10;                      // 0:A 1:B
    int row  = (id >> 3) & 127;
    int c16  = id & 7;                        // 16B chunk within 128B row
    const __half* base = (tile == 0) ? A : B;
    int r = ((tile == 0) ? m0 : n0) + row;
    const __half* src = base + (size_t)r * K + k0 + c16 * 8;
    uint32_t dst = stage + tile * TILE_B + (row << 7) + ((c16 ^ (row & 7)) << 4);
    asm volatile("cp.async.cg.shared.global [%0], [%1], 16;" :: "r"(dst), "l"(src) : "memory");
  }
  asm volatile("cp.async.commit_group;" ::: "memory");
}

template<int HALF_OUT>
__device__ __forceinline__ void gemm_core(
    const __half* __restrict__ A, const __half* __restrict__ B,
    void* __restrict__ C, int K, int ldc, int m0, int n0, char* smem)
{
  const uint32_t sb = smem_u32(smem);
  const int tid  = threadIdx.x;
  const int lane = tid & 31;
  const int wid  = tid >> 5;
  const int wm   = wid & 1;           // 2 m-blocks of 64
  const int wn   = wid >> 1;          // 4 n-blocks of 32
  const int NC = K >> 6;

  const int q     = lane >> 3;
  const int lrow  = (q & 1) * 8 + (lane & 7);
  const int khalf = q >> 1;

  float acc[4][4][4];
  #pragma unroll
  for (int a = 0; a < 4; a++)
    #pragma unroll
    for (int b = 0; b < 4; b++)
      #pragma unroll
      for (int d = 0; d < 4; d++) acc[a][b][d] = 0.f;

  load_stage(A, B, sb + 0 * STAGE_B, m0, n0, 0,  K, tid);
  load_stage(A, B, sb + 1 * STAGE_B, m0, n0, 64, K, tid);

  for (int c = 0; c < NC; c++) {
    asm volatile("cp.async.wait_group 1;" ::: "memory");
    __syncthreads();
    if (c + 2 < NC)
      load_stage(A, B, sb + ((c + 2) % STAGES) * STAGE_B,
                 m0, n0, (c + 2) * 64, K, tid);
    else
      asm volatile("cp.async.commit_group;" ::: "memory");   // keep group count uniform

    const uint32_t st = sb + (c % STAGES) * STAGE_B;
    #pragma unroll
    for (int ks = 0; ks < 4; ks++) {
      const int cc = 2 * ks + khalf;
      uint32_t af[4][4];
      #pragma unroll
      for (int mi = 0; mi < 4; mi++) {
        int r = wm * 64 + mi * 16 + lrow;
        uint32_t ad = st + (r << 7) + ((cc ^ (r & 7)) << 4);
        ldsm4(af[mi][0], af[mi][1], af[mi][2], af[mi][3], ad);
      }
      uint32_t bf[4][2];
      #pragma unroll
      for (int g = 0; g < 2; g++) {
        int r = wn * 32 + g * 16 + lrow;
        uint32_t bd = st + TILE_B + (r << 7) + ((cc ^ (r & 7)) << 4);
        uint32_t t0, t1, t2, t3;
        ldsm4(t0, t1, t2, t3, bd);
        bf[2*g][0] = t0; bf[2*g][1] = t2; bf[2*g+1][0] = t1; bf[2*g+1][1] = t3;
      }
      #pragma unroll
      for (int mi = 0; mi < 4; mi++)
        #pragma unroll
        for (int nj = 0; nj < 4; nj++)
          mma_f16(acc[mi][nj], af[mi], bf[nj]);
    }
  }

  #pragma unroll
  for (int mi = 0; mi < 4; mi++) {
    int r = m0 + wm * 64 + mi * 16 + (lane >> 2);
    #pragma unroll
    for (int nj = 0; nj < 4; nj++) {
      int col = n0 + wn * 32 + nj * 8 + ((lane & 3) << 1);
      if (HALF_OUT) {
        __half* Ch = (__half*)C;
        *(__half2*)&Ch[(size_t)r * ldc + col] =
            __floats2half2_rn(acc[mi][nj][0], acc[mi][nj][1]);
        *(__half2*)&Ch[(size_t)(r + 8) * ldc + col] =
            __floats2half2_rn(acc[mi][nj][2], acc[mi][nj][3]);
      } else {
        float* Cf = (float*)C;
        *(float2*)&Cf[(size_t)r * ldc + col]       = make_float2(acc[mi][nj][0], acc[mi][nj][1]);
        *(float2*)&Cf[(size_t)(r + 8) * ldc + col] = make_float2(acc[mi][nj][2], acc[mi][nj][3]);
      }
    }
  }
}

// projection GEMM: fp16 output
__global__ void __launch_bounds__(256, 2)
gemm_f16(const __half* __restrict__ A, const __half* __restrict__ B,
         __half* __restrict__ C, int K, int ldc)
{
  extern __shared__ char smem[];
  gemm_core<1>(A, B, C, K, ldc, blockIdx.x * 128, blockIdx.y * 128, smem);
}

// merged score GEMMs: z=0 -> QK*SK^T -> S ; z=1 -> QV*SV^T -> Wm  (fp32 out)
__global__ void __launch_bounds__(256, 2)
gemm_scores(const __half* __restrict__ QK, const __half* __restrict__ SK,
            float* __restrict__ S,
            const __half* __restrict__ QV, const __half* __restrict__ SV,
            float* __restrict__ Wm, int K, int ldc)
{
  extern __shared__ char smem[];
  const __half* A = blockIdx.z ? QV : QK;
  const __half* B = blockIdx.z ? SV : SK;
  float* C        = blockIdx.z ? Wm : S;
  gemm_core<0>(A, B, C, K, ldc, blockIdx.x * 128, blockIdx.y * 128, smem);
}

// ---------------- kernel 0: positional-encoding table (16K elems) ------------
__global__ void pe_build() {
  int idx = blockIdx.x * blockDim.x + threadIdx.x;
  if (idx >= SEQ * FEAT) return;
  int d  = idx & (FEAT - 1);
  int fr = idx >> 11;
  float freq = expf((float)(d & ~1) * (-9.210340371976184f / 2048.0f));
  float ang  = (float)fr * freq;
  d_PE[idx] = (d & 1) ? cosf(ang) : sinf(ang);
}

// ---------------- kernel 1: frames + PE -> fp16 (memory-bound) ---------------
__global__ void prep(const float* __restrict__ q, const float* __restrict__ s) {
  int idx = blockIdx.x * blockDim.x + threadIdx.x;
  if (idx >= MTP * FEAT) return;
  int r = idx >> 11;
  if (r >= RALL) { d_X[idx] = __float2half(0.f); return; }
  float v = (r < RQ) ? q[idx] : s[idx - (size_t)RQ * FEAT];
  d_X[idx] = __float2half(v + d_PE[idx & (SEQ * FEAT - 1)]);
}

// ---------------- kernel 2: transpose weights into [NTP, FEAT] fp16 ----------
__global__ void split_w(const float* __restrict__ kw, const float* __restrict__ vw) {
  __shared__ float tile[32][33];
  int p = blockIdx.z;
  const float* w = (p < 2) ? kw : vw;
  int k0 = blockIdx.x * 32, c0 = blockIdx.y * 32;
  int rbase = (p & 1) * FEAT;
  int tx = threadIdx.x, ty = threadIdx.y;  // 32 x 8
  #pragma unroll
  for (int i = 0; i < 32; i += 8)
    tile[ty + i][tx] = w[(size_t)(rbase + k0 + ty + i) * DOUT + c0 + tx];
  __syncthreads();
  #pragma unroll
  for (int i = 0; i < 32; i += 8) {
    size_t o = (size_t)(p * DOUT + c0 + ty + i) * FEAT + k0 + tx;
    d_Wt[o] = __float2half(tile[tx][ty + i]);
  }
}

// ---------------- kernel 3: fp32 sgemm, batched over z (Gram only) -----------
#define BM 64
#define BN 64
#define BK 16
__global__ void __launch_bounds__(256)
sgemm_nt_gram(const float* __restrict__ Abase, float* __restrict__ Cbase,
              int M, int N, int K, size_t strideA, size_t strideC) {
  const float* A = Abase + blockIdx.z * strideA;
  const float* B = A;
  float* C = Cbase + blockIdx.z * strideC;
  __shared__ __align__(16) float As[BK][BM + 4];
  __shared__ __align__(16) float Bs[BK][BN + 4];
  int tid = threadIdx.x;
  int tx = tid & 15, ty = tid >> 4;
  int m0 = blockIdx.x * BM, n0 = blockIdx.y * BN;
  int lr = tid >> 2;
  int lc = (tid & 3) << 2;
  float acc[4][4] = {};
  const float* Aptr = A + (size_t)(m0 + lr) * K + lc;
  const float* Bptr = B + (size_t)(n0 + lr) * K + lc;
  bool am = (m0 + lr) < M;
  bool bn = (n0 + lr) < N;
  for (int k0 = 0; k0 < K; k0 += BK) {
    float4 av = am ? *(const float4*)(Aptr + k0) : make_float4(0, 0, 0, 0);
    float4 bv = bn ? *(const float4*)(Bptr + k0) : make_float4(0, 0, 0, 0);
    As[lc + 0][lr] = av.x; As[lc + 1][lr] = av.y;
    As[lc + 2][lr] = av.z; As[lc + 3][lr] = av.w;
    Bs[lc + 0][lr] = bv.x; Bs[lc + 1][lr] = bv.y;
    Bs[lc + 2][lr] = bv.z; Bs[lc + 3][lr] = bv.w;
    __syncthreads();
    #pragma unroll
    for (int k = 0; k < BK; k++) {
      float4 a4 = *(const float4*)&As[k][ty << 2];
      float4 b4 = *(const float4*)&Bs[k][tx << 2];
      float ar[4] = {a4.x, a4.y, a4.z, a4.w};
      float br[4] = {b4.x, b4.y, b4.z, b4.w};
      #pragma unroll
      for (int i = 0; i < 4; i++)
        #pragma unroll
        for (int j = 0; j < 4; j++)
          acc[i][j] += ar[i] * br[j];
    }
    __syncthreads();
  }
  #pragma unroll
  for (int i = 0; i < 4; i++) {
    int m = m0 + (ty << 2) + i;
    if (m >= M) continue;
    #pragma unroll
    for (int j = 0; j < 4; j++) {
      int n = n0 + (tx << 2) + j;
      if (n < N) C[(size_t)m * N + n] = acc[i][j];
    }
  }
}

// ---------------- kernel 4: per-item combine, warp-parallel tuples -----------
// One block per clip; clip's 8 frame-rows of fp16 P staged in smem (74KB ->
// 2 CTAs/SM); each warp owns whole tuples -> warp-shuffle reductions only.
#define CSMEM (8*NTP*2)
__global__ void __launch_bounds__(256)
combine2(const float* __restrict__ kb, const float* __restrict__ vb,
         const float* __restrict__ gamma, const float* __restrict__ beta) {
  extern __shared__ __half sPh[];   // 8 * 4608 halves
  const int item = blockIdx.x;
  const bool isQ = item < NQv;
  const int tid = threadIdx.x;
  const int lane = tid & 31;
  const int w = tid >> 5;
  const __half* src = d_P + (size_t)item * SEQ * NTP;
  for (int i = tid * 8; i < SEQ * NTP; i += 256 * 8)
    *(uint4*)&sPh[i] = *(const uint4*)&src[i];
  __syncthreads();
  const int mBase = isQ ? item * TLEN : (item - NQv) * TLEN;
  for (int t = w; t < TLEN; t += 8) {
    const int fi = c_tup[2 * t], fj = c_tup[2 * t + 1];
    const __half* pA = sPh + fi * NTP;
    const __half* pB = sPh + fj * NTP;
    const size_t mOff = (size_t)(mBase + t) * DOUT;
    float xs[36];                   // DOUT = 36 * 32 exactly
    float s1 = 0.f, s2 = 0.f, qacc = 0.f;
    #pragma unroll
    for (int i = 0; i < 36; i++) {
      int d = lane + i * 32;
      float x = __half2float(pA[d]) + __half2float(pB[DOUT + d]) + kb[d];
      xs[i] = x; s1 += x; s2 += x * x;
      float y = __half2float(pA[2 * DOUT + d]) + __half2float(pB[3 * DOUT + d]) + vb[d];
      if (isQ) { d_QV[mOff + d] = __float2half(y); }
      else     { d_SV[mOff + d] = __float2half(y); d_SVf[mOff + d] = y; }
      qacc += y * y;
    }
    s1 = warpReduceSum(s1);
    s2 = warpReduceSum(s2);
    if (isQ) {
      qacc = warpReduceSum(qacc);
      if (lane == 0) d_qn[mBase + t] = qacc;
    }
    float mu  = s1 * (1.0f / DOUT);
    float var = s2 * (1.0f / DOUT) - mu * mu;
    float inv = rsqrtf(var + 1e-5f);
    #pragma unroll
    for (int i = 0; i < 36; i++) {
      int d = lane + i * 32;
      float z = (xs[i] - mu) * inv * gamma[d] + beta[d];
      if (isQ) d_QK[mOff + d] = __float2half(z);
      else     d_SK[mOff + d] = __float2half(z);
    }
  }
}

// ---------------- kernel 5: softmax + Gram quadratic form + logits -----------
// Block = (2 queries, class c), 256 threads; Gram load amortized over 2 queries.
#define QPB 2
#define FSMEM ((19600 + QPB*TLEN*140 + 8) * 4)
__global__ void __launch_bounds__(256)
finalize_k(const float* __restrict__ gt, const float* __restrict__ tw,
           float* __restrict__ out) {
  extern __shared__ float sm[];
  float* Gs  = sm;                  // 19600
  float* es  = sm + 19600;          // QPB * 28 * 140
  float* red = es + QPB * TLEN * 140;  // 8
  const int qb = blockIdx.x, c = blockIdx.y;
  const int tid = threadIdx.x;
  const int lane = tid & 31;
  const int w = tid >> 5;
  const float* Gsrc = d_G + (size_t)c * 19600;
  for (int idx = tid * 4; idx < 19600; idx += 256 * 4)
    *(float4*)&Gs[idx] = *(const float4*)&Gsrc[idx];
  __syncthreads();

  const float gscale = gt[0] * tw[0];
  #pragma unroll
  for (int qi = 0; qi < QPB; qi++) {
    const int qq = qb * QPB + qi;
    float* e_q = es + qi * TLEN * 140;
    float dist = 0.f;
    if (w < 7) {
      const float scale = rsqrtf((float)DOUT);
      const int t0 = w * 4;
      float Zs[4], TWs[4];
      // ---- phase 1: softmax stats for this warp's 4 tuples ----
      #pragma unroll
      for (int tt = 0; tt < 4; tt++) {
        const int m = qq * TLEN + t0 + tt;
        const float* Srow = d_S  + (size_t)m * MSP + c * 140;
        const float* Wrow = d_Wm + (size_t)m * MSP + c * 140;
        float ev[5];
        float lmax = -INFINITY;
        #pragma unroll
        for (int i = 0; i < 5; i++) {
          int j = lane + i * 32;
          if (j < 140) { ev[i] = Srow[j] * scale; lmax = fmaxf(lmax, ev[i]); }
          else ev[i] = -INFINITY;
        }
        lmax = warpReduceMax(lmax);
        float lsum = 0.f, lw = 0.f;
        #pragma unroll
        for (int i = 0; i < 5; i++) {
          int j = lane + i * 32;
          if (j < 140) {
            float e = __expf(ev[i] - lmax);
            e_q[(t0 + tt) * 140 + j] = e;
            lsum += e;
            lw   += e * Wrow[j];
          }
        }
        Zs[tt]  = warpReduceSum(lsum);
        TWs[tt] = warpReduceSum(lw);
      }
      __syncwarp();
      // ---- phase 2: quadratic forms for 4 tuples simultaneously ----
      float hq[5][4];
      #pragma unroll
      for (int i = 0; i < 5; i++)
        #pragma unroll
        for (int tt = 0; tt < 4; tt++) hq[i][tt] = 0.f;
      for (int j = 0; j < 140; j++) {
        float e4[4];
        #pragma unroll
        for (int tt = 0; tt < 4; tt++) e4[tt] = e_q[(t0 + tt) * 140 + j];
        const float* Grow = Gs + j * 140;
        #pragma unroll
        for (int i = 0; i < 5; i++) {
          int jc = lane + i * 32;
          float g = (jc < 140) ? Grow[jc] : 0.f;
          #pragma unroll
          for (int tt = 0; tt < 4; tt++) hq[i][tt] += g * e4[tt];
        }
      }
      #pragma unroll
      for (int tt = 0; tt < 4; tt++) {
        float qp = 0.f;
        #pragma unroll
        for (int i = 0; i < 5; i++) {
          int jc = lane + i * 32;
          if (jc < 140) qp += hq[i][tt] * e_q[(t0 + tt) * 140 + jc];
        }
        qp = warpReduceSum(qp);
        float invZ = 1.0f / Zs[tt];
        dist += d_qn[qq * TLEN + t0 + tt] - 2.f * TWs[tt] * invZ + qp * invZ * invZ;
      }
    }
    if (lane == 0) red[w] = dist;
    __syncthreads();
    if (tid == 0) {
      float s = 0.f;
      #pragma unroll
      for (int i = 0; i < 7; i++) s += red[i];
      out[qq * WAY + c] = -(s * (1.0f / TLEN)) * gscale;
    }
    __syncthreads();     // red reuse guard for next query
  }
}

// ---------------- launcher ---------------------------------------------------
extern "C" void kernel_launch(void* const* d_in, const int* in_sizes, int n_in,
                              void* d_out, int out_size) {
  const float* support = (const float*)d_in[0];
  /* d_in[1] = support_labels: sorted & balanced; reference uses a reshape */
  const float* queries = (const float*)d_in[2];
  const float* kw    = (const float*)d_in[3];
  const float* kb    = (const float*)d_in[4];
  const float* vw    = (const float*)d_in[5];
  const float* vb    = (const float*)d_in[6];
  const float* gamma = (const float*)d_in[7];
  const float* beta  = (const float*)d_in[8];
  const float* gt    = (const float*)d_in[9];
  const float* tw    = (const float*)d_in[10];
  float* out = (float*)d_out;

  __half *X, *Wt, *P, *QK, *QV, *SK, *SV;
  float *SVf, *S, *Wm, *G;
  cudaGetSymbolAddress((void**)&X,   d_X);
  cudaGetSymbolAddress((void**)&Wt,  d_Wt);
  cudaGetSymbolAddress((void**)&P,   d_P);
  cudaGetSymbolAddress((void**)&QK,  d_QK);
  cudaGetSymbolAddress((void**)&QV,  d_QV);
  cudaGetSymbolAddress((void**)&SK,  d_SK);
  cudaGetSymbolAddress((void**)&SV,  d_SV);
  cudaGetSymbolAddress((void**)&SVf, d_SVf);
  cudaGetSymbolAddress((void**)&S,   d_S);
  cudaGetSymbolAddress((void**)&Wm,  d_Wm);
  cudaGetSymbolAddress((void**)&G,   d_G);

  cudaFuncSetAttribute(gemm_f16,    cudaFuncAttributeMaxDynamicSharedMemorySize, GSMEM);
  cudaFuncSetAttribute(gemm_scores, cudaFuncAttributeMaxDynamicSharedMemorySize, GSMEM);
  cudaFuncSetAttribute(combine2,    cudaFuncAttributeMaxDynamicSharedMemorySize, CSMEM);
  cudaFuncSetAttribute(finalize_k,  cudaFuncAttributeMaxDynamicSharedMemorySize, FSMEM);

  // launch 0: PE table (16K elems)
  pe_build<<<(SEQ * FEAT + 255) / 256, 256>>>();
  // launch 1: frames + PE -> fp16 (memory-bound)
  prep<<<(MTP * FEAT + 255) / 256, 256>>>(queries, support);
  // launch 2: weights -> [4608, 2048] K-contiguous fp16
  split_w<<<dim3(FEAT / 32, DOUT / 32, 4), dim3(32, 8)>>>(kw, vw);
  // launch 3 (ncu-captured): all 4 projection planes, fp16 output
  gemm_f16<<<dim3(MTP / 128, NTP / 128), 256, GSMEM>>>(X, Wt, P, FEAT, NTP);
  // per-item tuple combine + LN + fp16 casts (warp-parallel tuples, 2 CTA/SM)
  combine2<<<NQv + NSv, 256, CSMEM>>>(kb, vb, gamma, beta);
  // per-class value Gram matrices (fp32, tiny, batched over z)
  sgemm_nt_gram<<<dim3(3, 3, WAY), 256>>>(SVf, G, 140, 140, DOUT,
                                          (size_t)140 * DOUT, (size_t)19600);
  // merged scores + value-overlap GEMMs: [14080,1152]x[768,1152]^T, z=2
  gemm_scores<<<dim3(MQP / 128, MSP / 128, 2), 256, GSMEM>>>(
      QK, SK, S, QV, SV, Wm, DOUT, MSP);
  // softmax + quadratic-form distance + logits (2 queries per block)
  finalize_k<<<dim3(NQv / QPB, WAY), 256, FSMEM>>>(gt, tw, out);
}

// round 11
// speedup vs baseline: 6.0158x; 1.0663x over previous
#include <cuda_runtime.h>
#include <cuda_fp16.h>
#include <cstdint>
#include <math.h>

#define SEQ   8
#define FEAT  2048
#define DOUT  1152
#define TLEN  28
#define WAY   5
#define SHOT  5
#define NQv   500
#define NSv   25
#define RQ    (NQv*SEQ)     /* 4000 query frame rows   */
#define RS    (NSv*SEQ)     /* 200 support frame rows  */
#define RALL  (RQ+RS)       /* 4200                    */
#define MQ    (NQv*TLEN)    /* 14000 query tuples      */
#define MS    (NSv*TLEN)    /* 700 support tuples      */

// padded dims (multiples of 128 for the tensor GEMM; no bounds checks needed)
#define MTP   4224          /* padded frame rows                  */
#define NTP   4608          /* 4 planes x 1152 output cols        */
#define MQP   14080         /* padded query tuples                */
#define MSP   768           /* padded support tuples              */

// ---------------- scratch (static device memory; no allocations) -------------
__device__ float   d_PE [SEQ*FEAT];          // positional encoding table
__device__ __half  d_X  [MTP*FEAT];
__device__ __half  d_Wt [NTP*FEAT];
__device__ __half  d_P  [(size_t)MTP*NTP];   // 4-plane frame projections (fp16)
__device__ __half  d_QK [(size_t)MQP*DOUT];
__device__ __half  d_QV [(size_t)MQP*DOUT];
__device__ __half  d_SK [(size_t)MSP*DOUT];
__device__ __half  d_SV [(size_t)MSP*DOUT];
__device__ float   d_SVf[(size_t)MSP*DOUT];
__device__ float   d_S  [(size_t)MQP*MSP];
__device__ float   d_Wm [(size_t)MQP*MSP];
__device__ float   d_qn [MQ];
__device__ float   d_Gp [20*140*140];        // per-(class,kseg) Gram partials
__device__ float   d_G  [WAY*140*140];

__constant__ int c_tup[TLEN*2] = {
  0,1, 0,2, 0,3, 0,4, 0,5, 0,6, 0,7,
  1,2, 1,3, 1,4, 1,5, 1,6, 1,7,
  2,3, 2,4, 2,5, 2,6, 2,7,
  3,4, 3,5, 3,6, 3,7,
  4,5, 4,6, 4,7,
  5,6, 5,7,
  6,7
};

// ======================= generic-target helpers ==============================
__device__ __forceinline__ uint32_t smem_u32(const void* p) {
  uint32_t a;
  asm("{ .reg .u64 t; cvta.to.shared.u64 t, %1; cvt.u32.u64 %0, t; }" : "=r"(a) : "l"(p));
  return a;
}
__device__ __forceinline__ void ldsm4(uint32_t& r0, uint32_t& r1, uint32_t& r2,
                                      uint32_t& r3, uint32_t a) {
  asm volatile("ldmatrix.sync.aligned.m8n8.x4.shared.b16 {%0,%1,%2,%3}, [%4];"
               : "=r"(r0), "=r"(r1), "=r"(r2), "=r"(r3) : "r"(a));
}
__device__ __forceinline__ void mma_f16(float* c, const uint32_t* a, const uint32_t* b) {
  asm volatile("mma.sync.aligned.m16n8k16.row.col.f32.f16.f16.f32 "
               "{%0,%1,%2,%3}, {%4,%5,%6,%7}, {%8,%9}, {%0,%1,%2,%3};"
               : "+f"(c[0]), "+f"(c[1]), "+f"(c[2]), "+f"(c[3])
               : "r"(a[0]), "r"(a[1]), "r"(a[2]), "r"(a[3]), "r"(b[0]), "r"(b[1]));
}
__device__ __forceinline__ float warpReduceSum(float v) {
  #pragma unroll
  for (int o = 16; o; o >>= 1) v += __shfl_xor_sync(0xffffffffu, v, o);
  return v;
}
__device__ __forceinline__ float warpReduceMax(float v) {
  #pragma unroll
  for (int o = 16; o; o >>= 1) v = fmaxf(v, __shfl_xor_sync(0xffffffffu, v, o));
  return v;
}

// ======================= fp16 HMMA GEMM (single product) =====================
#define STAGES  3
#define TILE_B  16384                 /* 128 rows x 64 fp16 (128B rows) */
#define STAGE_B (2*TILE_B)            /* A tile + B tile = 32KB */
#define GSMEM   (STAGES*STAGE_B)      /* 96 KB -> 2 CTAs/SM */

__device__ __forceinline__ void load_stage(
    const __half* __restrict__ A, const __half* __restrict__ B,
    uint32_t stage, int m0, int n0, int k0, int K, int tid)
{
  #pragma unroll
  for (int i = 0; i < 8; i++) {
    int id   = tid + i * 256;
    int tile = id >> 10;                      // 0:A 1:B
    int row  = (id >> 3) & 127;
    int c16  = id & 7;                        // 16B chunk within 128B row
    const __half* base = (tile == 0) ? A : B;
    int r = ((tile == 0) ? m0 : n0) + row;
    const __half* src = base + (size_t)r * K + k0 + c16 * 8;
    uint32_t dst = stage + tile * TILE_B + (row << 7) + ((c16 ^ (row & 7)) << 4);
    asm volatile("cp.async.cg.shared.global [%0], [%1], 16;" :: "r"(dst), "l"(src) : "memory");
  }
  asm volatile("cp.async.commit_group;" ::: "memory");
}

template<int HALF_OUT>
__device__ __forceinline__ void gemm_core(
    const __half* __restrict__ A, const __half* __restrict__ B,
    void* __restrict__ C, int K, int ldc, int m0, int n0, char* smem)
{
  const uint32_t sb = smem_u32(smem);
  const int tid  = threadIdx.x;
  const int lane = tid & 31;
  const int wid  = tid >> 5;
  const int wm   = wid & 1;           // 2 m-blocks of 64
  const int wn   = wid >> 1;          // 4 n-blocks of 32
  const int NC = K >> 6;

  const int q     = lane >> 3;
  const int lrow  = (q & 1) * 8 + (lane & 7);
  const int khalf = q >> 1;

  // smem reuse guard for persistent callers (all warps past previous tile)
  __syncthreads();

  float acc[4][4][4];
  #pragma unroll
  for (int a = 0; a < 4; a++)
    #pragma unroll
    for (int b = 0; b < 4; b++)
      #pragma unroll
      for (int d = 0; d < 4; d++) acc[a][b][d] = 0.f;

  load_stage(A, B, sb + 0 * STAGE_B, m0, n0, 0,  K, tid);
  load_stage(A, B, sb + 1 * STAGE_B, m0, n0, 64, K, tid);

  for (int c = 0; c < NC; c++) {
    asm volatile("cp.async.wait_group 1;" ::: "memory");
    __syncthreads();
    if (c + 2 < NC)
      load_stage(A, B, sb + ((c + 2) % STAGES) * STAGE_B,
                 m0, n0, (c + 2) * 64, K, tid);
    else
      asm volatile("cp.async.commit_group;" ::: "memory");   // keep group count uniform

    const uint32_t st = sb + (c % STAGES) * STAGE_B;
    #pragma unroll
    for (int ks = 0; ks < 4; ks++) {
      const int cc = 2 * ks + khalf;
      uint32_t af[4][4];
      #pragma unroll
      for (int mi = 0; mi < 4; mi++) {
        int r = wm * 64 + mi * 16 + lrow;
        uint32_t ad = st + (r << 7) + ((cc ^ (r & 7)) << 4);
        ldsm4(af[mi][0], af[mi][1], af[mi][2], af[mi][3], ad);
      }
      uint32_t bf[4][2];
      #pragma unroll
      for (int g = 0; g < 2; g++) {
        int r = wn * 32 + g * 16 + lrow;
        uint32_t bd = st + TILE_B + (r << 7) + ((cc ^ (r & 7)) << 4);
        uint32_t t0, t1, t2, t3;
        ldsm4(t0, t1, t2, t3, bd);
        bf[2*g][0] = t0; bf[2*g][1] = t2; bf[2*g+1][0] = t1; bf[2*g+1][1] = t3;
      }
      #pragma unroll
      for (int mi = 0; mi < 4; mi++)
        #pragma unroll
        for (int nj = 0; nj < 4; nj++)
          mma_f16(acc[mi][nj], af[mi], bf[nj]);
    }
  }

  #pragma unroll
  for (int mi = 0; mi < 4; mi++) {
    int r = m0 + wm * 64 + mi * 16 + (lane >> 2);
    #pragma unroll
    for (int nj = 0; nj < 4; nj++) {
      int col = n0 + wn * 32 + nj * 8 + ((lane & 3) << 1);
      if (HALF_OUT) {
        __half* Ch = (__half*)C;
        *(__half2*)&Ch[(size_t)r * ldc + col] =
            __floats2half2_rn(acc[mi][nj][0], acc[mi][nj][1]);
        *(__half2*)&Ch[(size_t)(r + 8) * ldc + col] =
            __floats2half2_rn(acc[mi][nj][2], acc[mi][nj][3]);
      } else {
        float* Cf = (float*)C;
        *(float2*)&Cf[(size_t)r * ldc + col]       = make_float2(acc[mi][nj][0], acc[mi][nj][1]);
        *(float2*)&Cf[(size_t)(r + 8) * ldc + col] = make_float2(acc[mi][nj][2], acc[mi][nj][3]);
      }
    }
  }
}

// projection GEMM: fp16 output
__global__ void __launch_bounds__(256, 2)
gemm_f16(const __half* __restrict__ A, const __half* __restrict__ B,
         __half* __restrict__ C, int K, int ldc)
{
  extern __shared__ char smem[];
  gemm_core<1>(A, B, C, K, ldc, blockIdx.x * 128, blockIdx.y * 128, smem);
}

// persistent merged score GEMMs: tile z=0 -> QK*SK^T -> S ; z=1 -> QV*SV^T -> Wm
#define SC_MT (MQP/128)     /* 110 */
#define SC_NT (MSP/128)     /* 6   */
#define SC_TILES (SC_MT*SC_NT*2)
__global__ void __launch_bounds__(256, 2)
gemm_scores(const __half* __restrict__ QK, const __half* __restrict__ SK,
            float* __restrict__ S,
            const __half* __restrict__ QV, const __half* __restrict__ SV,
            float* __restrict__ Wm, int K, int ldc)
{
  extern __shared__ char smem[];
  for (int tile = blockIdx.x; tile < SC_TILES; tile += gridDim.x) {
    int z  = tile / (SC_MT * SC_NT);
    int t2 = tile % (SC_MT * SC_NT);
    int mi = t2 % SC_MT;                // m-major: concurrent blocks share B panel
    int ni = t2 / SC_MT;
    const __half* A = z ? QV : QK;
    const __half* B = z ? SV : SK;
    float* C        = z ? Wm : S;
    gemm_core<0>(A, B, C, K, ldc, mi * 128, ni * 128, smem);
  }
}

// ---------------- kernel 0: PE table + weight transpose (fused) --------------
// z 0..3 -> transpose plane z ; z==4 -> build PE table
__global__ void pre_w(const float* __restrict__ kw, const float* __restrict__ vw) {
  if (blockIdx.z < 4) {
    __shared__ float tile[32][33];
    int p = blockIdx.z;
    const float* w = (p < 2) ? kw : vw;
    int k0 = blockIdx.x * 32, c0 = blockIdx.y * 32;
    int rbase = (p & 1) * FEAT;
    int tx = threadIdx.x, ty = threadIdx.y;  // 32 x 8
    #pragma unroll
    for (int i = 0; i < 32; i += 8)
      tile[ty + i][tx] = w[(size_t)(rbase + k0 + ty + i) * DOUT + c0 + tx];
    __syncthreads();
    #pragma unroll
    for (int i = 0; i < 32; i += 8) {
      size_t o = (size_t)(p * DOUT + c0 + ty + i) * FEAT + k0 + tx;
      d_Wt[o] = __float2half(tile[tx][ty + i]);
    }
  } else {
    int bid = blockIdx.y * gridDim.x + blockIdx.x;
    int t = bid * 256 + threadIdx.y * 32 + threadIdx.x;
    if (t < SEQ * FEAT) {
      int d  = t & (FEAT - 1);
      int fr = t >> 11;
      float freq = expf((float)(d & ~1) * (-9.210340371976184f / 2048.0f));
      float ang  = (float)fr * freq;
      d_PE[t] = (d & 1) ? cosf(ang) : sinf(ang);
    }
  }
}

// ---------------- kernel 1: frames + PE -> fp16, vectorized x8 ---------------
__global__ void prep(const float* __restrict__ q, const float* __restrict__ s) {
  int i8 = (blockIdx.x * 256 + threadIdx.x) * 8;
  if (i8 >= MTP * FEAT) return;
  int r = i8 >> 11;
  __half h[8];
  if (r >= RALL) {
    #pragma unroll
    for (int i = 0; i < 8; i++) h[i] = __float2half(0.f);
  } else {
    const float* src = (r < RQ) ? (q + i8) : (s + (i8 - RQ * FEAT));
    float4 a = *(const float4*)src;
    float4 b = *(const float4*)(src + 4);
    const float* pe = d_PE + (i8 & (SEQ * FEAT - 1));
    float4 p0 = *(const float4*)pe;
    float4 p1 = *(const float4*)(pe + 4);
    h[0] = __float2half(a.x + p0.x); h[1] = __float2half(a.y + p0.y);
    h[2] = __float2half(a.z + p0.z); h[3] = __float2half(a.w + p0.w);
    h[4] = __float2half(b.x + p1.x); h[5] = __float2half(b.y + p1.y);
    h[6] = __float2half(b.z + p1.z); h[7] = __float2half(b.w + p1.w);
  }
  *(uint4*)&d_X[i8] = *(const uint4*)h;
}

// ---------------- Gram: K-split partials (fp32) + reduce ---------------------
#define BM 64
#define BN 64
#define BK 16
#define KSEG 288
__global__ void __launch_bounds__(256)
gram_part(const float* __restrict__ Abase) {
  const int z = blockIdx.z;                // 0..19 = class*4 + kseg
  const int cls = z >> 2, seg = z & 3;
  const float* A = Abase + (size_t)cls * 140 * DOUT + seg * KSEG;
  const float* B = A;
  float* C = d_Gp + (size_t)z * 19600;
  __shared__ __align__(16) float As[BK][BM + 4];
  __shared__ __align__(16) float Bs[BK][BN + 4];
  int tid = threadIdx.x;
  int tx = tid & 15, ty = tid >> 4;
  int m0 = blockIdx.x * BM, n0 = blockIdx.y * BN;
  int lr = tid >> 2;
  int lc = (tid & 3) << 2;
  float acc[4][4] = {};
  const float* Aptr = A + (size_t)(m0 + lr) * DOUT + lc;
  const float* Bptr = B + (size_t)(n0 + lr) * DOUT + lc;
  bool am = (m0 + lr) < 140;
  bool bn = (n0 + lr) < 140;
  for (int k0 = 0; k0 < KSEG; k0 += BK) {
    float4 av = am ? *(const float4*)(Aptr + k0) : make_float4(0, 0, 0, 0);
    float4 bv = bn ? *(const float4*)(Bptr + k0) : make_float4(0, 0, 0, 0);
    As[lc + 0][lr] = av.x; As[lc + 1][lr] = av.y;
    As[lc + 2][lr] = av.z; As[lc + 3][lr] = av.w;
    Bs[lc + 0][lr] = bv.x; Bs[lc + 1][lr] = bv.y;
    Bs[lc + 2][lr] = bv.z; Bs[lc + 3][lr] = bv.w;
    __syncthreads();
    #pragma unroll
    for (int k = 0; k < BK; k++) {
      float4 a4 = *(const float4*)&As[k][ty << 2];
      float4 b4 = *(const float4*)&Bs[k][tx << 2];
      float ar[4] = {a4.x, a4.y, a4.z, a4.w};
      float br[4] = {b4.x, b4.y, b4.z, b4.w};
      #pragma unroll
      for (int i = 0; i < 4; i++)
        #pragma unroll
        for (int j = 0; j < 4; j++)
          acc[i][j] += ar[i] * br[j];
    }
    __syncthreads();
  }
  #pragma unroll
  for (int i = 0; i < 4; i++) {
    int m = m0 + (ty << 2) + i;
    if (m >= 140) continue;
    #pragma unroll
    for (int j = 0; j < 4; j++) {
      int n = n0 + (tx << 2) + j;
      if (n < 140) C[(size_t)m * 140 + n] = acc[i][j];
    }
  }
}
__global__ void gram_reduce() {
  int i = (blockIdx.x * 256 + threadIdx.x) * 4;
  if (i >= WAY * 19600) return;
  int cls = i / 19600, off = i % 19600;
  const float* base = d_Gp + (size_t)cls * 4 * 19600 + off;
  float4 s0 = *(const float4*)(base);
  float4 s1 = *(const float4*)(base + 19600);
  float4 s2 = *(const float4*)(base + 2 * 19600);
  float4 s3 = *(const float4*)(base + 3 * 19600);
  float4 r;
  r.x = (s0.x + s1.x) + (s2.x + s3.x);
  r.y = (s0.y + s1.y) + (s2.y + s3.y);
  r.z = (s0.z + s1.z) + (s2.z + s3.z);
  r.w = (s0.w + s1.w) + (s2.w + s3.w);
  *(float4*)&d_G[i] = r;
}

// ---------------- kernel: per-item combine, warp-parallel tuples -------------
#define CSMEM (8*NTP*2)
__global__ void __launch_bounds__(256)
combine2(const float* __restrict__ kb, const float* __restrict__ vb,
         const float* __restrict__ gamma, const float* __restrict__ beta) {
  extern __shared__ __half sPh[];   // 8 * 4608 halves
  const int item = blockIdx.x;
  const bool isQ = item < NQv;
  const int tid = threadIdx.x;
  const int lane = tid & 31;
  const int w = tid >> 5;
  const __half* src = d_P + (size_t)item * SEQ * NTP;
  for (int i = tid * 8; i < SEQ * NTP; i += 256 * 8)
    *(uint4*)&sPh[i] = *(const uint4*)&src[i];
  __syncthreads();
  const int mBase = isQ ? item * TLEN : (item - NQv) * TLEN;
  for (int t = w; t < TLEN; t += 8) {
    const int fi = c_tup[2 * t], fj = c_tup[2 * t + 1];
    const __half* pA = sPh + fi * NTP;
    const __half* pB = sPh + fj * NTP;
    const size_t mOff = (size_t)(mBase + t) * DOUT;
    float xs[36];                   // DOUT = 36 * 32 exactly
    float s1 = 0.f, s2 = 0.f, qacc = 0.f;
    #pragma unroll
    for (int i = 0; i < 36; i++) {
      int d = lane + i * 32;
      float x = __half2float(pA[d]) + __half2float(pB[DOUT + d]) + kb[d];
      xs[i] = x; s1 += x; s2 += x * x;
      float y = __half2float(pA[2 * DOUT + d]) + __half2float(pB[3 * DOUT + d]) + vb[d];
      if (isQ) { d_QV[mOff + d] = __float2half(y); }
      else     { d_SV[mOff + d] = __float2half(y); d_SVf[mOff + d] = y; }
      qacc += y * y;
    }
    s1 = warpReduceSum(s1);
    s2 = warpReduceSum(s2);
    if (isQ) {
      qacc = warpReduceSum(qacc);
      if (lane == 0) d_qn[mBase + t] = qacc;
    }
    float mu  = s1 * (1.0f / DOUT);
    float var = s2 * (1.0f / DOUT) - mu * mu;
    float inv = rsqrtf(var + 1e-5f);
    #pragma unroll
    for (int i = 0; i < 36; i++) {
      int d = lane + i * 32;
      float z = (xs[i] - mu) * inv * gamma[d] + beta[d];
      if (isQ) d_QK[mOff + d] = __float2half(z);
      else     d_SK[mOff + d] = __float2half(z);
    }
  }
}

// ---------------- finalize: softmax + Gram quadratic form + logits -----------
#define QPB 2
#define FSMEM ((19600 + QPB*TLEN*140 + 8) * 4)
__global__ void __launch_bounds__(256)
finalize_k(const float* __restrict__ gt, const float* __restrict__ tw,
           float* __restrict__ out) {
  extern __shared__ float sm[];
  float* Gs  = sm;                  // 19600
  float* es  = sm + 19600;          // QPB * 28 * 140
  float* red = es + QPB * TLEN * 140;  // 8
  const int qb = blockIdx.x, c = blockIdx.y;
  const int tid = threadIdx.x;
  const int lane = tid & 31;
  const int w = tid >> 5;
  const float* Gsrc = d_G + (size_t)c * 19600;
  for (int idx = tid * 4; idx < 19600; idx += 256 * 4)
    *(float4*)&Gs[idx] = *(const float4*)&Gsrc[idx];
  __syncthreads();

  const float gscale = gt[0] * tw[0];
  #pragma unroll
  for (int qi = 0; qi < QPB; qi++) {
    const int qq = qb * QPB + qi;
    float* e_q = es + qi * TLEN * 140;
    float dist = 0.f;
    if (w < 7) {
      const float scale = rsqrtf((float)DOUT);
      const int t0 = w * 4;
      float Zs[4], TWs[4];
      #pragma unroll
      for (int tt = 0; tt < 4; tt++) {
        const int m = qq * TLEN + t0 + tt;
        const float* Srow = d_S  + (size_t)m * MSP + c * 140;
        const float* Wrow = d_Wm + (size_t)m * MSP + c * 140;
        float ev[5];
        float lmax = -INFINITY;
        #pragma unroll
        for (int i = 0; i < 5; i++) {
          int j = lane + i * 32;
          if (j < 140) { ev[i] = Srow[j] * scale; lmax = fmaxf(lmax, ev[i]); }
          else ev[i] = -INFINITY;
        }
        lmax = warpReduceMax(lmax);
        float lsum = 0.f, lw = 0.f;
        #pragma unroll
        for (int i = 0; i < 5; i++) {
          int j = lane + i * 32;
          if (j < 140) {
            float e = __expf(ev[i] - lmax);
            e_q[(t0 + tt) * 140 + j] = e;
            lsum += e;
            lw   += e * Wrow[j];
          }
        }
        Zs[tt]  = warpReduceSum(lsum);
        TWs[tt] = warpReduceSum(lw);
      }
      __syncwarp();
      float hq[5][4];
      #pragma unroll
      for (int i = 0; i < 5; i++)
        #pragma unroll
        for (int tt = 0; tt < 4; tt++) hq[i][tt] = 0.f;
      for (int j = 0; j < 140; j++) {
        float e4[4];
        #pragma unroll
        for (int tt = 0; tt < 4; tt++) e4[tt] = e_q[(t0 + tt) * 140 + j];
        const float* Grow = Gs + j * 140;
        #pragma unroll
        for (int i = 0; i < 5; i++) {
          int jc = lane + i * 32;
          float g = (jc < 140) ? Grow[jc] : 0.f;
          #pragma unroll
          for (int tt = 0; tt < 4; tt++) hq[i][tt] += g * e4[tt];
        }
      }
      #pragma unroll
      for (int tt = 0; tt < 4; tt++) {
        float qp = 0.f;
        #pragma unroll
        for (int i = 0; i < 5; i++) {
          int jc = lane + i * 32;
          if (jc < 140) qp += hq[i][tt] * e_q[(t0 + tt) * 140 + jc];
        }
        qp = warpReduceSum(qp);
        float invZ = 1.0f / Zs[tt];
        dist += d_qn[qq * TLEN + t0 + tt] - 2.f * TWs[tt] * invZ + qp * invZ * invZ;
      }
    }
    if (lane == 0) red[w] = dist;
    __syncthreads();
    if (tid == 0) {
      float s = 0.f;
      #pragma unroll
      for (int i = 0; i < 7; i++) s += red[i];
      out[qq * WAY + c] = -(s * (1.0f / TLEN)) * gscale;
    }
    __syncthreads();     // red reuse guard for next query
  }
}

// ---------------- launcher ---------------------------------------------------
extern "C" void kernel_launch(void* const* d_in, const int* in_sizes, int n_in,
                              void* d_out, int out_size) {
  const float* support = (const float*)d_in[0];
  /* d_in[1] = support_labels: sorted & balanced; reference uses a reshape */
  const float* queries = (const float*)d_in[2];
  const float* kw    = (const float*)d_in[3];
  const float* kb    = (const float*)d_in[4];
  const float* vw    = (const float*)d_in[5];
  const float* vb    = (const float*)d_in[6];
  const float* gamma = (const float*)d_in[7];
  const float* beta  = (const float*)d_in[8];
  const float* gt    = (const float*)d_in[9];
  const float* tw    = (const float*)d_in[10];
  float* out = (float*)d_out;

  __half *X, *Wt, *P, *QK, *QV, *SK, *SV;
  float *SVf, *S, *Wm;
  cudaGetSymbolAddress((void**)&X,   d_X);
  cudaGetSymbolAddress((void**)&Wt,  d_Wt);
  cudaGetSymbolAddress((void**)&P,   d_P);
  cudaGetSymbolAddress((void**)&QK,  d_QK);
  cudaGetSymbolAddress((void**)&QV,  d_QV);
  cudaGetSymbolAddress((void**)&SK,  d_SK);
  cudaGetSymbolAddress((void**)&SV,  d_SV);
  cudaGetSymbolAddress((void**)&SVf, d_SVf);
  cudaGetSymbolAddress((void**)&S,   d_S);
  cudaGetSymbolAddress((void**)&Wm,  d_Wm);

  cudaFuncSetAttribute(gemm_f16,    cudaFuncAttributeMaxDynamicSharedMemorySize, GSMEM);
  cudaFuncSetAttribute(gemm_scores, cudaFuncAttributeMaxDynamicSharedMemorySize, GSMEM);
  cudaFuncSetAttribute(combine2,    cudaFuncAttributeMaxDynamicSharedMemorySize, CSMEM);
  cudaFuncSetAttribute(finalize_k,  cudaFuncAttributeMaxDynamicSharedMemorySize, FSMEM);

  // launch 0: fused PE table + weight transpose
  pre_w<<<dim3(FEAT / 32, DOUT / 32, 5), dim3(32, 8)>>>(kw, vw);
  // launch 1: frames + PE -> fp16 (vectorized x8)
  prep<<<(MTP * FEAT / 8 + 255) / 256, 256>>>(queries, support);
  // launch 2: all 4 projection planes, fp16 output
  gemm_f16<<<dim3(MTP / 128, NTP / 128), 256, GSMEM>>>(X, Wt, P, FEAT, NTP);
  // launch 3 (ncu-captured): per-item tuple combine + LN + fp16 casts
  combine2<<<NQv + NSv, 256, CSMEM>>>(kb, vb, gamma, beta);
  // per-class value Gram partials (K-split x4) + reduce
  gram_part<<<dim3(3, 3, 20), 256>>>(SVf);
  gram_reduce<<<(WAY * 19600 / 4 + 255) / 256, 256>>>();
  // persistent merged scores + value-overlap GEMMs
  gemm_scores<<<296, 256, GSMEM>>>(QK, SK, S, QV, SV, Wm, DOUT, MSP);
  // softmax + quadratic-form distance + logits (2 queries per block)
  finalize_k<<<dim3(NQv / QPB, WAY), 256, FSMEM>>>(gt, tw, out);
}